// round 9
// baseline (speedup 1.0000x reference)
#include <cuda_runtime.h>
#include <cuda_fp16.h>
#include <math.h>
#include <stdint.h>

// ---------------------------------------------------------------------------
// Problem constants
// ---------------------------------------------------------------------------
constexpr int BB = 2;
constexpr int TT = 1024;
constexpr int CC = 1024;
constexpr int HH = 16;
constexpr int DD = 64;
constexpr int HT = HH * TT;  // 16384

constexpr int NSPLIT = 4;    // stage-4 head splits

// ---------------------------------------------------------------------------
// Device scratch
// ---------------------------------------------------------------------------
__device__ float  g_S   [(size_t)BB * TT * HT];     // fp32 scores
__device__ __half g_P   [(size_t)BB * TT * HT];     // softmax probs (fp16)
__device__ __half g_Zt  [(size_t)BB * CC * HT];     // Z^T fp16 [b][e][h*T+s]
__device__ __half g_Xhi [(size_t)BB * TT * CC];     // x hi
__device__ __half g_Xlo [(size_t)BB * TT * CC];     // x lo (scores only)
__device__ __half g_Wt  [(size_t)HH * CC * CC];     // W^T fp16 [h][e][k]
__device__ float  g_Opart[NSPLIT][(size_t)BB * TT * CC]; // stage-4 partials

// ---------------------------------------------------------------------------
// Baseline-PTX helpers (compute_103-safe; no "a"-only features)
// ---------------------------------------------------------------------------
__device__ __forceinline__ uint32_t smem_u32(const void* p) {
    uint32_t a;
    asm("{ .reg .u64 t; cvta.to.shared.u64 t, %1; cvt.u32.u64 %0, t; }" : "=r"(a) : "l"(p));
    return a;
}
__device__ __forceinline__ void cp16(uint32_t saddr, const void* g) {
    asm volatile("cp.async.cg.shared.global [%0], [%1], 16;" :: "r"(saddr), "l"(g));
}
__device__ __forceinline__ void cp_commit() {
    asm volatile("cp.async.commit_group;" ::: "memory");
}
template <int N>
__device__ __forceinline__ void cp_wait() {
    asm volatile("cp.async.wait_group %0;" :: "n"(N) : "memory");
}
#define LDSM4(R, A)                                                               \
    asm volatile("ldmatrix.sync.aligned.m8n8.x4.shared.b16 {%0,%1,%2,%3}, [%4];"  \
                 : "=r"((R)[0]), "=r"((R)[1]), "=r"((R)[2]), "=r"((R)[3]) : "r"(A))

__device__ __forceinline__ void mma_fp16(float* c, const uint32_t* a, const uint32_t* b) {
    asm volatile(
        "mma.sync.aligned.m16n8k16.row.col.f32.f16.f16.f32 "
        "{%0,%1,%2,%3},{%4,%5,%6,%7},{%8,%9},{%0,%1,%2,%3};"
        : "+f"(c[0]), "+f"(c[1]), "+f"(c[2]), "+f"(c[3])
        : "r"(a[0]), "r"(a[1]), "r"(a[2]), "r"(a[3]), "r"(b[0]), "r"(b[1]));
}

// ---------------------------------------------------------------------------
// Conversions
// ---------------------------------------------------------------------------
__global__ void convert_x_kernel(const float* __restrict__ x) {
    size_t n = (size_t)BB * TT * CC;
    for (size_t i = (size_t)blockIdx.x * blockDim.x + threadIdx.x; i < n;
         i += (size_t)gridDim.x * blockDim.x) {
        float f = x[i];
        __half hi = __float2half_rn(f);
        g_Xhi[i] = hi;
        g_Xlo[i] = __float2half_rn(f - __half2float(hi));
    }
}

// W[h*CC + k][e] -> Wt[h][e][k] (single fp16)
__global__ void convert_w_kernel(const float* __restrict__ w) {
    __shared__ float t[32][33];
    int h = blockIdx.z;
    int e0 = blockIdx.x * 32, k0 = blockIdx.y * 32;
    int tx = threadIdx.x, ty = threadIdx.y;  // (32, 8)
#pragma unroll
    for (int r = 0; r < 4; r++) {
        int k = k0 + ty + r * 8;
        t[ty + r * 8][tx] = w[(size_t)(h * CC + k) * CC + e0 + tx];
    }
    __syncthreads();
#pragma unroll
    for (int r = 0; r < 4; r++) {
        int e = e0 + ty + r * 8;
        size_t idx = (size_t)h * CC * CC + (size_t)e * CC + k0 + tx;
        g_Wt[idx] = __float2half_rn(t[tx][ty + r * 8]);
    }
}

// ---------------------------------------------------------------------------
// Softmax: row softmax over s<=t -> fp16 P; only touches s < roundup(t+1,128)
// ---------------------------------------------------------------------------
__global__ __launch_bounds__(256) void softmax_kernel() {
    __shared__ float red[8];
    int row = blockIdx.x;
    int t = (row / HH) & (TT - 1);
    int limit = ((t >> 7) + 1) << 7;  // causal extent rounded to 128
    const float* p = g_S + (size_t)row * TT;
    __half* po = g_P + (size_t)row * TT;
    int tid = threadIdx.x;

    float v[4];
    float m = -INFINITY;
#pragma unroll
    for (int j = 0; j < 4; j++) {
        int s = tid + j * 256;
        if (s <= t) { v[j] = p[s]; m = fmaxf(m, v[j]); }
        else v[j] = -INFINITY;
    }
#pragma unroll
    for (int o = 16; o; o >>= 1) m = fmaxf(m, __shfl_xor_sync(0xffffffffu, m, o));
    if ((tid & 31) == 0) red[tid >> 5] = m;
    __syncthreads();
    if (tid < 32) {
        float mm = (tid < 8) ? red[tid] : -INFINITY;
#pragma unroll
        for (int o = 4; o; o >>= 1) mm = fmaxf(mm, __shfl_xor_sync(0xffffffffu, mm, o));
        if (tid == 0) red[0] = mm;
    }
    __syncthreads();
    m = red[0];
    __syncthreads();

    float sum = 0.0f;
#pragma unroll
    for (int j = 0; j < 4; j++) {
        int s = tid + j * 256;
        if (s <= t) { v[j] = __expf(v[j] - m); sum += v[j]; }
        else v[j] = 0.0f;
    }
#pragma unroll
    for (int o = 16; o; o >>= 1) sum += __shfl_xor_sync(0xffffffffu, sum, o);
    if ((tid & 31) == 0) red[tid >> 5] = sum;
    __syncthreads();
    if (tid < 32) {
        float ss = (tid < 8) ? red[tid] : 0.0f;
#pragma unroll
        for (int o = 4; o; o >>= 1) ss += __shfl_xor_sync(0xffffffffu, ss, o);
        if (tid == 0) red[0] = ss;
    }
    __syncthreads();
    float inv = 1.0f / red[0];

#pragma unroll
    for (int j = 0; j < 4; j++) {
        int s = tid + j * 256;
        if (s < limit) po[s] = __float2half_rn(v[j] * inv);
    }
}

// ---------------------------------------------------------------------------
// HMMA fp16 GEMM template. 128x128 tile, K-chunk 64, cp.async pipeline.
// STAGE==1: scores  S = Y Y^T (K=64, 1 chunk), hi/lo 3-pass -> g_S fp32
// STAGE==3: Z^T = (x @ W_h)^T, single-pass fp16 -> g_Zt fp16
// STAGE==4: out = P @ Z, 4-way head split + LPT -> g_Opart
// ---------------------------------------------------------------------------
constexpr int KCH = 64;                     // K per chunk
constexpr int TSTRIDE = 144;                // 128B row + 16B pad
constexpr int TILE_B = 128 * TSTRIDE;       // 18432

template <int STAGE>
__global__ __launch_bounds__(256, 1) void mma_gemm(float* __restrict__ Out) {
    if (STAGE == 1 && blockIdx.x > blockIdx.y) return;  // above-diagonal tile

    constexpr int NA = (STAGE == 1) ? 2 : 1;   // # A tiles (hi[,lo])
    constexpr int NB = (STAGE == 1) ? 2 : 1;   // # B tiles (hi[,lo])
    constexpr int BUF_B = (NA + NB) * TILE_B;
    constexpr int NBUF = (STAGE == 1) ? 2 : 4; // stage 1: NC==1

    extern __shared__ char sp[];
    const uint32_t sbase = smem_u32(sp);

    const int tid = threadIdx.x;
    const int lane = tid & 31;
    const int wid = tid >> 5;
    const int wm = wid & 3;      // 4 warps along M (32 rows each)
    const int wn = wid >> 2;     // 2 warps along N (64 cols each)
    // LPT: stage 4 runs heavy tiles (large by) first
    const int by = (STAGE == 4) ? (gridDim.y - 1 - blockIdx.y) : blockIdx.y;
    const int m0 = by * 128, n0 = blockIdx.x * 128;

    int b, h = 0, part = 0;
    const __half *A0, *A1 = nullptr, *B0, *B1 = nullptr;
    size_t ldA, ldB;
    int NC, kph = 0;
    if (STAGE == 1) {
        int z = blockIdx.z; b = z >> 4; h = z & 15;
        A0 = g_Xhi + (size_t)b * TT * CC + h * DD;
        A1 = g_Xlo + (size_t)b * TT * CC + h * DD;
        B0 = A0; B1 = A1; ldA = CC; ldB = CC;
        NC = 1;
    } else if (STAGE == 3) {
        int z = blockIdx.z; b = z >> 4; h = z & 15;
        A0 = g_Xhi + (size_t)b * TT * CC; ldA = CC;
        B0 = g_Wt + (size_t)h * CC * CC; ldB = CC;
        NC = CC / KCH;                      // 16
    } else {
        int z = blockIdx.z; b = z >> 2; part = z & 3;
        A0 = g_P + (size_t)b * TT * HT; ldA = HT;
        B0 = g_Zt + (size_t)b * CC * HT; ldB = HT;
        kph = (by + 1) * 2;                 // kept 64-wide chunks per head
        NC = (HH / NSPLIT) * kph;           // 4 heads per split
    }

    auto kk_of = [&](int i) -> int {
        if (STAGE == 4) return (part * (HH / NSPLIT) + i / kph) * TT + (i % kph) * KCH;
        return i * KCH;
    };

    // loader: per tile 128 rows x 128 bytes; 2 threads/row, 4x cp16 each
    const int lr = tid >> 1;
    const int lq = (tid & 1) * 64;          // byte offset within row
    auto load_tiles = [&](int i, int buf) {
        int kk = kk_of(i);
        uint32_t sb = sbase + buf * BUF_B + lr * TSTRIDE + lq;
        size_t offA = (size_t)(m0 + lr) * ldA + kk + lq / 2;
        size_t offB = (size_t)(n0 + lr) * ldB + kk + lq / 2;
#pragma unroll
        for (int q = 0; q < 4; q++) {
            cp16(sb + q * 16, A0 + offA + q * 8);
            if (NA == 2) cp16(sb + TILE_B + q * 16, A1 + offA + q * 8);
            cp16(sb + NA * TILE_B + q * 16, B0 + offB + q * 8);
            if (NB == 2) cp16(sb + (NA + 1) * TILE_B + q * 16, B1 + offB + q * 8);
        }
    };

    float acc[2][8][4];
#pragma unroll
    for (int i = 0; i < 2; i++)
#pragma unroll
        for (int j = 0; j < 8; j++)
#pragma unroll
            for (int k = 0; k < 4; k++) acc[i][j][k] = 0.0f;

    // prologue: always NBUF-1 committed groups (empty groups complete trivially)
#pragma unroll
    for (int j = 0; j < NBUF - 1; j++) {
        if (j < NC) load_tiles(j, j);
        cp_commit();
    }

    for (int i = 0; i < NC; ++i) {
        cp_wait<NBUF - 2>();
        __syncthreads();

        const uint32_t base = sbase + (i & (NBUF - 1)) * BUF_B;
#pragma unroll
        for (int ks = 0; ks < KCH / 16; ks++) {
            uint32_t afr[NA][2][4], bfr[NB][4][4];
#pragma unroll
            for (int mt = 0; mt < 2; mt++) {
                uint32_t a = base + (uint32_t)(wm * 32 + mt * 16 + (lane & 15)) * TSTRIDE
                             + ((lane >> 4) << 4) + ks * 32;
                LDSM4(afr[0][mt], a);
                if (NA == 2) LDSM4(afr[1][mt], a + TILE_B);
            }
#pragma unroll
            for (int q = 0; q < 4; q++) {
                uint32_t a = base + NA * TILE_B
                             + (uint32_t)(wn * 64 + q * 16 + ((lane >> 4) << 3) + (lane & 7)) * TSTRIDE
                             + (((lane >> 3) & 1) << 4) + ks * 32;
                LDSM4(bfr[0][q], a);
                if (NB == 2) LDSM4(bfr[1][q], a + TILE_B);
            }
            // compensation passes: skip lo*lo
#pragma unroll
            for (int ia = 0; ia < NA; ia++)
#pragma unroll
                for (int ib = 0; ib < NB; ib++) {
                    if (ia + ib == 2) continue;
#pragma unroll
                    for (int mt = 0; mt < 2; mt++)
#pragma unroll
                        for (int q = 0; q < 4; q++) {
                            mma_fp16(acc[mt][2 * q],     afr[ia][mt], &bfr[ib][q][0]);
                            mma_fp16(acc[mt][2 * q + 1], afr[ia][mt], &bfr[ib][q][2]);
                        }
                }
        }
        if (i + NBUF - 1 < NC) load_tiles(i + NBUF - 1, (i + NBUF - 1) & (NBUF - 1));
        cp_commit();
    }
    cp_wait<0>();
    __syncthreads();

    if (STAGE == 1) {
        float* Cp = g_S + (size_t)b * TT * HT + (size_t)h * TT;
#pragma unroll
        for (int mt = 0; mt < 2; mt++)
#pragma unroll
            for (int nt = 0; nt < 8; nt++)
#pragma unroll
                for (int ci = 0; ci < 4; ci++) {
                    int row = m0 + wm * 32 + mt * 16 + (lane >> 2) + (ci >> 1) * 8;
                    int col = n0 + wn * 64 + nt * 8 + ((lane & 3) << 1) + (ci & 1);
                    Cp[(size_t)row * HT + col] =
                        (col <= row) ? acc[mt][nt][ci] * 0.25f : -1e30f;
                }
    } else if (STAGE == 4) {
        float* ob = Out + ((size_t)part * BB + b) * TT * CC;
#pragma unroll
        for (int mt = 0; mt < 2; mt++)
#pragma unroll
            for (int nt = 0; nt < 8; nt++) {
                int row = m0 + wm * 32 + mt * 16 + (lane >> 2);
                int col = n0 + wn * 64 + nt * 8 + ((lane & 3) << 1);
                *reinterpret_cast<float2*>(&ob[(size_t)row * CC + col]) =
                    make_float2(acc[mt][nt][0], acc[mt][nt][1]);
                *reinterpret_cast<float2*>(&ob[(size_t)(row + 8) * CC + col]) =
                    make_float2(acc[mt][nt][2], acc[mt][nt][3]);
            }
    } else {
        // STAGE 3: transpose through smem, then coalesced Z^T fp16 stores
        constexpr int TROW = 272;             // 128*2 + 16 pad
#pragma unroll
        for (int mt = 0; mt < 2; mt++)
#pragma unroll
            for (int nt = 0; nt < 8; nt++)
#pragma unroll
                for (int ci = 0; ci < 4; ci++) {
                    int row = wm * 32 + mt * 16 + (lane >> 2) + (ci >> 1) * 8;  // m
                    int col = wn * 64 + nt * 8 + ((lane & 3) << 1) + (ci & 1);  // e
                    *reinterpret_cast<__half*>(sp + col * TROW + row * 2) =
                        __float2half_rn(acc[mt][nt][ci]);
                }
        __syncthreads();
        size_t gb = (size_t)b * CC * HT + (size_t)h * TT + m0;
        for (int idx = tid; idx < 128 * 16; idx += 256) {
            int r = idx >> 4, cch = idx & 15;
            uint4 v = *reinterpret_cast<uint4*>(sp + r * TROW + cch * 16);
            *reinterpret_cast<uint4*>(&g_Zt[gb + (size_t)(n0 + r) * HT + cch * 8]) = v;
        }
    }
}

// ---------------------------------------------------------------------------
// Sum the four stage-4 head-split partials into the final output.
// ---------------------------------------------------------------------------
__global__ void add_out_kernel(float* __restrict__ out) {
    size_t n = (size_t)BB * TT * CC / 4;
    const float4* p0 = reinterpret_cast<const float4*>(g_Opart[0]);
    const float4* p1 = reinterpret_cast<const float4*>(g_Opart[1]);
    const float4* p2 = reinterpret_cast<const float4*>(g_Opart[2]);
    const float4* p3 = reinterpret_cast<const float4*>(g_Opart[3]);
    float4* o = reinterpret_cast<float4*>(out);
    for (size_t i = (size_t)blockIdx.x * blockDim.x + threadIdx.x; i < n;
         i += (size_t)gridDim.x * blockDim.x) {
        float4 a = p0[i], bq = p1[i], c = p2[i], d = p3[i];
        o[i] = make_float4((a.x + bq.x) + (c.x + d.x), (a.y + bq.y) + (c.y + d.y),
                           (a.z + bq.z) + (c.z + d.z), (a.w + bq.w) + (c.w + d.w));
    }
}

// ---------------------------------------------------------------------------
extern "C" void kernel_launch(void* const* d_in, const int* in_sizes, int n_in,
                              void* d_out, int out_size) {
    const float* x = (const float*)d_in[0];
    // d_in[1]: boolean causal mask == triu(k=1); applied analytically in-kernel.
    const float* w = (const float*)d_in[2];
    float* out = (float*)d_out;

    constexpr int DSMEM1 = 2 * 4 * TILE_B;   // 147456 (NBUF=2, 4 tiles)
    constexpr int DSMEM34 = 4 * 2 * TILE_B;  // 147456 (NBUF=4, 2 tiles)

    cudaFuncSetAttribute(mma_gemm<1>, cudaFuncAttributeMaxDynamicSharedMemorySize, DSMEM1);
    cudaFuncSetAttribute(mma_gemm<3>, cudaFuncAttributeMaxDynamicSharedMemorySize, DSMEM34);
    cudaFuncSetAttribute(mma_gemm<4>, cudaFuncAttributeMaxDynamicSharedMemorySize, DSMEM34);

    float* o0;
    cudaGetSymbolAddress((void**)&o0, g_Opart);

    convert_x_kernel<<<2048, 256>>>(x);
    convert_w_kernel<<<dim3(32, 32, 16), dim3(32, 8)>>>(w);
    mma_gemm<1><<<dim3(TT / 128, TT / 128, BB * HH), 256, DSMEM1>>>(nullptr);
    softmax_kernel<<<BB * TT * HH, 256>>>();
    mma_gemm<3><<<dim3(CC / 128, TT / 128, BB * HH), 256, DSMEM34>>>(nullptr);
    mma_gemm<4><<<dim3(CC / 128, TT / 128, BB * NSPLIT), 256, DSMEM34>>>(o0);
    add_out_kernel<<<1024, 256>>>(out);
}

// round 10
// speedup vs baseline: 1.0810x; 1.0810x over previous
#include <cuda_runtime.h>
#include <cuda_fp16.h>
#include <math.h>
#include <stdint.h>

// ---------------------------------------------------------------------------
// Problem constants
// ---------------------------------------------------------------------------
constexpr int BB = 2;
constexpr int TT = 1024;
constexpr int CC = 1024;
constexpr int HH = 16;
constexpr int DD = 64;
constexpr int HT = HH * TT;  // 16384

constexpr int NSPLIT = 4;    // stage-4 head splits

// ---------------------------------------------------------------------------
// Device scratch
// ---------------------------------------------------------------------------
__device__ float  g_S   [(size_t)BB * TT * HT];     // fp32 scores
__device__ __half g_P   [(size_t)BB * TT * HT];     // softmax probs (fp16)
__device__ __half g_Zt  [(size_t)BB * CC * HT];     // Z^T fp16 [b][e][h*T+s]
__device__ __half g_Xhi [(size_t)BB * TT * CC];     // x hi
__device__ __half g_Xlo [(size_t)BB * TT * CC];     // x lo (scores only)
__device__ __half g_Wt  [(size_t)HH * CC * CC];     // W^T fp16 [h][e][k]
__device__ float  g_Opart[NSPLIT][(size_t)BB * TT * CC]; // stage-4 partials

// ---------------------------------------------------------------------------
// Baseline-PTX helpers (compute_103-safe; no "a"-only features)
// ---------------------------------------------------------------------------
__device__ __forceinline__ uint32_t smem_u32(const void* p) {
    uint32_t a;
    asm("{ .reg .u64 t; cvta.to.shared.u64 t, %1; cvt.u32.u64 %0, t; }" : "=r"(a) : "l"(p));
    return a;
}
__device__ __forceinline__ void cp16(uint32_t saddr, const void* g) {
    asm volatile("cp.async.cg.shared.global [%0], [%1], 16;" :: "r"(saddr), "l"(g));
}
__device__ __forceinline__ void cp_commit() {
    asm volatile("cp.async.commit_group;" ::: "memory");
}
template <int N>
__device__ __forceinline__ void cp_wait() {
    asm volatile("cp.async.wait_group %0;" :: "n"(N) : "memory");
}
#define LDSM4(R, A)                                                               \
    asm volatile("ldmatrix.sync.aligned.m8n8.x4.shared.b16 {%0,%1,%2,%3}, [%4];"  \
                 : "=r"((R)[0]), "=r"((R)[1]), "=r"((R)[2]), "=r"((R)[3]) : "r"(A))

__device__ __forceinline__ void mma_fp16(float* c, const uint32_t* a, const uint32_t* b) {
    asm volatile(
        "mma.sync.aligned.m16n8k16.row.col.f32.f16.f16.f32 "
        "{%0,%1,%2,%3},{%4,%5,%6,%7},{%8,%9},{%0,%1,%2,%3};"
        : "+f"(c[0]), "+f"(c[1]), "+f"(c[2]), "+f"(c[3])
        : "r"(a[0]), "r"(a[1]), "r"(a[2]), "r"(a[3]), "r"(b[0]), "r"(b[1]));
}

// ---------------------------------------------------------------------------
// Conversions
// ---------------------------------------------------------------------------
__global__ void convert_x_kernel(const float* __restrict__ x) {
    size_t n = (size_t)BB * TT * CC;
    for (size_t i = (size_t)blockIdx.x * blockDim.x + threadIdx.x; i < n;
         i += (size_t)gridDim.x * blockDim.x) {
        float f = x[i];
        __half hi = __float2half_rn(f);
        g_Xhi[i] = hi;
        g_Xlo[i] = __float2half_rn(f - __half2float(hi));
    }
}

// W[h*CC + k][e] -> Wt[h][e][k] (single fp16)
__global__ void convert_w_kernel(const float* __restrict__ w) {
    __shared__ float t[32][33];
    int h = blockIdx.z;
    int e0 = blockIdx.x * 32, k0 = blockIdx.y * 32;
    int tx = threadIdx.x, ty = threadIdx.y;  // (32, 8)
#pragma unroll
    for (int r = 0; r < 4; r++) {
        int k = k0 + ty + r * 8;
        t[ty + r * 8][tx] = w[(size_t)(h * CC + k) * CC + e0 + tx];
    }
    __syncthreads();
#pragma unroll
    for (int r = 0; r < 4; r++) {
        int e = e0 + ty + r * 8;
        size_t idx = (size_t)h * CC * CC + (size_t)e * CC + k0 + tx;
        g_Wt[idx] = __float2half_rn(t[tx][ty + r * 8]);
    }
}

// ---------------------------------------------------------------------------
// Softmax: row softmax over s<=t -> fp16 P; only touches s < roundup(t+1,128)
// ---------------------------------------------------------------------------
__global__ __launch_bounds__(256) void softmax_kernel() {
    __shared__ float red[8];
    int row = blockIdx.x;
    int t = (row / HH) & (TT - 1);
    int limit = ((t >> 7) + 1) << 7;  // causal extent rounded to 128
    const float* p = g_S + (size_t)row * TT;
    __half* po = g_P + (size_t)row * TT;
    int tid = threadIdx.x;

    float v[4];
    float m = -INFINITY;
#pragma unroll
    for (int j = 0; j < 4; j++) {
        int s = tid + j * 256;
        if (s <= t) { v[j] = p[s]; m = fmaxf(m, v[j]); }
        else v[j] = -INFINITY;
    }
#pragma unroll
    for (int o = 16; o; o >>= 1) m = fmaxf(m, __shfl_xor_sync(0xffffffffu, m, o));
    if ((tid & 31) == 0) red[tid >> 5] = m;
    __syncthreads();
    if (tid < 32) {
        float mm = (tid < 8) ? red[tid] : -INFINITY;
#pragma unroll
        for (int o = 4; o; o >>= 1) mm = fmaxf(mm, __shfl_xor_sync(0xffffffffu, mm, o));
        if (tid == 0) red[0] = mm;
    }
    __syncthreads();
    m = red[0];
    __syncthreads();

    float sum = 0.0f;
#pragma unroll
    for (int j = 0; j < 4; j++) {
        int s = tid + j * 256;
        if (s <= t) { v[j] = __expf(v[j] - m); sum += v[j]; }
        else v[j] = 0.0f;
    }
#pragma unroll
    for (int o = 16; o; o >>= 1) sum += __shfl_xor_sync(0xffffffffu, sum, o);
    if ((tid & 31) == 0) red[tid >> 5] = sum;
    __syncthreads();
    if (tid < 32) {
        float ss = (tid < 8) ? red[tid] : 0.0f;
#pragma unroll
        for (int o = 4; o; o >>= 1) ss += __shfl_xor_sync(0xffffffffu, ss, o);
        if (tid == 0) red[0] = ss;
    }
    __syncthreads();
    float inv = 1.0f / red[0];

#pragma unroll
    for (int j = 0; j < 4; j++) {
        int s = tid + j * 256;
        if (s < limit) po[s] = __float2half_rn(v[j] * inv);
    }
}

// ---------------------------------------------------------------------------
// HMMA fp16 GEMM template (R8 config). 128x128 tile, K-chunk 32, 4-stage pipe.
// STAGE==1: scores  S = Y Y^T (K=64), hi/lo 3-pass, mask*0.25 -> g_S fp32
// STAGE==3: Z^T = (x @ W_h)^T, single-pass fp16 -> g_Zt fp16
// STAGE==4: out = P @ Z, 4-way head split + LPT -> g_Opart
// ---------------------------------------------------------------------------
constexpr int TSTRIDE = 80;               // padded smem row (bytes)
constexpr int TILE_B = 128 * TSTRIDE;     // 10240
constexpr int NBUF = 4;

template <int STAGE>
__global__ __launch_bounds__(256, 1) void mma_gemm(float* __restrict__ Out) {
    if (STAGE == 1 && blockIdx.x > blockIdx.y) return;  // above-diagonal tile

    constexpr int NA = (STAGE == 1) ? 2 : 1;   // # A tiles (hi[,lo])
    constexpr int NB = (STAGE == 1) ? 2 : 1;   // # B tiles (hi[,lo])
    constexpr int BUF_B = (NA + NB) * TILE_B;

    extern __shared__ char sp[];
    const uint32_t sbase = smem_u32(sp);

    const int tid = threadIdx.x;
    const int lane = tid & 31;
    const int wid = tid >> 5;
    const int wm = wid & 3;      // 4 warps along M (32 rows each)
    const int wn = wid >> 2;     // 2 warps along N (64 cols each)
    // LPT: stage 4 runs heavy tiles (large by) first
    const int by = (STAGE == 4) ? (gridDim.y - 1 - blockIdx.y) : blockIdx.y;
    const int m0 = by * 128, n0 = blockIdx.x * 128;

    int b, h = 0, part = 0;
    const __half *A0, *A1 = nullptr, *B0, *B1 = nullptr;
    size_t ldA, ldB;
    int NC, kph = 0;
    if (STAGE == 1) {
        int z = blockIdx.z; b = z >> 4; h = z & 15;
        A0 = g_Xhi + (size_t)b * TT * CC + h * DD;
        A1 = g_Xlo + (size_t)b * TT * CC + h * DD;
        B0 = A0; B1 = A1; ldA = CC; ldB = CC;
        NC = 2;
    } else if (STAGE == 3) {
        int z = blockIdx.z; b = z >> 4; h = z & 15;
        A0 = g_Xhi + (size_t)b * TT * CC; ldA = CC;
        B0 = g_Wt + (size_t)h * CC * CC; ldB = CC;
        NC = 32;
    } else {
        int z = blockIdx.z; b = z >> 2; part = z & 3;
        A0 = g_P + (size_t)b * TT * HT; ldA = HT;
        B0 = g_Zt + (size_t)b * CC * HT; ldB = HT;
        kph = (by + 1) * 4;                // kept 32-chunks per head (causal)
        NC = (HH / NSPLIT) * kph;          // 4 heads per split
    }

    auto kk_of = [&](int i) -> int {
        if (STAGE == 4) return (part * (HH / NSPLIT) + i / kph) * TT + (i % kph) * 32;
        return i * 32;
    };

    const int lr = tid >> 1;
    const int lc = (tid & 1) * 2;
    auto load_tiles = [&](int i, int buf) {
        int kk = kk_of(i);
        uint32_t sb = sbase + buf * BUF_B + lr * TSTRIDE + lc * 16;
        size_t offA = (size_t)(m0 + lr) * ldA + kk + lc * 8;
        size_t offB = (size_t)(n0 + lr) * ldB + kk + lc * 8;
        cp16(sb, A0 + offA);
        cp16(sb + 16, A0 + offA + 8);
        if (NA == 2) {
            cp16(sb + TILE_B, A1 + offA);
            cp16(sb + TILE_B + 16, A1 + offA + 8);
        }
        cp16(sb + NA * TILE_B, B0 + offB);
        cp16(sb + NA * TILE_B + 16, B0 + offB + 8);
        if (NB == 2) {
            cp16(sb + (NA + 1) * TILE_B, B1 + offB);
            cp16(sb + (NA + 1) * TILE_B + 16, B1 + offB + 8);
        }
    };

    float acc[2][8][4];
#pragma unroll
    for (int i = 0; i < 2; i++)
#pragma unroll
        for (int j = 0; j < 8; j++)
#pragma unroll
            for (int k = 0; k < 4; k++) acc[i][j][k] = 0.0f;

    // prologue: always NBUF-1 committed groups (empty groups complete trivially)
#pragma unroll
    for (int j = 0; j < NBUF - 1; j++) {
        if (j < NC) load_tiles(j, j);
        cp_commit();
    }

    for (int i = 0; i < NC; ++i) {
        cp_wait<NBUF - 2>();
        __syncthreads();

        const uint32_t base = sbase + (i & (NBUF - 1)) * BUF_B;
#pragma unroll
        for (int ks = 0; ks < 2; ks++) {
            uint32_t afr[NA][2][4], bfr[NB][4][4];
#pragma unroll
            for (int mt = 0; mt < 2; mt++) {
                uint32_t a = base + (uint32_t)(wm * 32 + mt * 16 + (lane & 15)) * TSTRIDE
                             + ((lane >> 4) << 4) + ks * 32;
                LDSM4(afr[0][mt], a);
                if (NA == 2) LDSM4(afr[1][mt], a + TILE_B);
            }
#pragma unroll
            for (int q = 0; q < 4; q++) {
                uint32_t a = base + NA * TILE_B
                             + (uint32_t)(wn * 64 + q * 16 + ((lane >> 4) << 3) + (lane & 7)) * TSTRIDE
                             + (((lane >> 3) & 1) << 4) + ks * 32;
                LDSM4(bfr[0][q], a);
                if (NB == 2) LDSM4(bfr[1][q], a + TILE_B);
            }
            // compensation passes: skip lo*lo
#pragma unroll
            for (int ia = 0; ia < NA; ia++)
#pragma unroll
                for (int ib = 0; ib < NB; ib++) {
                    if (ia + ib == 2) continue;
#pragma unroll
                    for (int mt = 0; mt < 2; mt++)
#pragma unroll
                        for (int q = 0; q < 4; q++) {
                            mma_fp16(acc[mt][2 * q],     afr[ia][mt], &bfr[ib][q][0]);
                            mma_fp16(acc[mt][2 * q + 1], afr[ia][mt], &bfr[ib][q][2]);
                        }
                }
        }
        if (i + NBUF - 1 < NC) load_tiles(i + NBUF - 1, (i + NBUF - 1) & (NBUF - 1));
        cp_commit();
    }
    cp_wait<0>();
    __syncthreads();

    if (STAGE == 1) {
        float* Cp = g_S + (size_t)b * TT * HT + (size_t)h * TT;
#pragma unroll
        for (int mt = 0; mt < 2; mt++)
#pragma unroll
            for (int nt = 0; nt < 8; nt++)
#pragma unroll
                for (int ci = 0; ci < 4; ci++) {
                    int row = m0 + wm * 32 + mt * 16 + (lane >> 2) + (ci >> 1) * 8;
                    int col = n0 + wn * 64 + nt * 8 + ((lane & 3) << 1) + (ci & 1);
                    Cp[(size_t)row * HT + col] =
                        (col <= row) ? acc[mt][nt][ci] * 0.25f : -1e30f;
                }
    } else if (STAGE == 4) {
        float* ob = Out + ((size_t)part * BB + b) * TT * CC;
#pragma unroll
        for (int mt = 0; mt < 2; mt++)
#pragma unroll
            for (int nt = 0; nt < 8; nt++) {
                int row = m0 + wm * 32 + mt * 16 + (lane >> 2);
                int col = n0 + wn * 64 + nt * 8 + ((lane & 3) << 1);
                *reinterpret_cast<float2*>(&ob[(size_t)row * CC + col]) =
                    make_float2(acc[mt][nt][0], acc[mt][nt][1]);
                *reinterpret_cast<float2*>(&ob[(size_t)(row + 8) * CC + col]) =
                    make_float2(acc[mt][nt][2], acc[mt][nt][3]);
            }
    } else {
        // STAGE 3: transpose through smem, then coalesced Z^T fp16 stores
        constexpr int TROW = 272;             // 128*2 + 16 pad
#pragma unroll
        for (int mt = 0; mt < 2; mt++)
#pragma unroll
            for (int nt = 0; nt < 8; nt++)
#pragma unroll
                for (int ci = 0; ci < 4; ci++) {
                    int row = wm * 32 + mt * 16 + (lane >> 2) + (ci >> 1) * 8;  // m
                    int col = wn * 64 + nt * 8 + ((lane & 3) << 1) + (ci & 1);  // e
                    *reinterpret_cast<__half*>(sp + col * TROW + row * 2) =
                        __float2half_rn(acc[mt][nt][ci]);
                }
        __syncthreads();
        size_t gb = (size_t)b * CC * HT + (size_t)h * TT + m0;
        for (int idx = tid; idx < 128 * 16; idx += 256) {
            int r = idx >> 4, cch = idx & 15;
            uint4 v = *reinterpret_cast<uint4*>(sp + r * TROW + cch * 16);
            *reinterpret_cast<uint4*>(&g_Zt[gb + (size_t)(n0 + r) * HT + cch * 8]) = v;
        }
    }
}

// ---------------------------------------------------------------------------
// Sum the four stage-4 head-split partials into the final output.
// ---------------------------------------------------------------------------
__global__ void add_out_kernel(float* __restrict__ out) {
    size_t n = (size_t)BB * TT * CC / 4;
    const float4* p0 = reinterpret_cast<const float4*>(g_Opart[0]);
    const float4* p1 = reinterpret_cast<const float4*>(g_Opart[1]);
    const float4* p2 = reinterpret_cast<const float4*>(g_Opart[2]);
    const float4* p3 = reinterpret_cast<const float4*>(g_Opart[3]);
    float4* o = reinterpret_cast<float4*>(out);
    for (size_t i = (size_t)blockIdx.x * blockDim.x + threadIdx.x; i < n;
         i += (size_t)gridDim.x * blockDim.x) {
        float4 a = p0[i], bq = p1[i], c = p2[i], d = p3[i];
        o[i] = make_float4((a.x + bq.x) + (c.x + d.x), (a.y + bq.y) + (c.y + d.y),
                           (a.z + bq.z) + (c.z + d.z), (a.w + bq.w) + (c.w + d.w));
    }
}

// ---------------------------------------------------------------------------
extern "C" void kernel_launch(void* const* d_in, const int* in_sizes, int n_in,
                              void* d_out, int out_size) {
    const float* x = (const float*)d_in[0];
    // d_in[1]: boolean causal mask == triu(k=1); applied analytically in-kernel.
    const float* w = (const float*)d_in[2];
    float* out = (float*)d_out;

    constexpr int DSMEM1 = NBUF * 4 * TILE_B;  // 163840 (NA=2, NB=2)
    constexpr int DSMEM34 = NBUF * 2 * TILE_B; // 81920  (NA=1, NB=1)

    cudaFuncSetAttribute(mma_gemm<1>, cudaFuncAttributeMaxDynamicSharedMemorySize, DSMEM1);
    cudaFuncSetAttribute(mma_gemm<3>, cudaFuncAttributeMaxDynamicSharedMemorySize, DSMEM34);
    cudaFuncSetAttribute(mma_gemm<4>, cudaFuncAttributeMaxDynamicSharedMemorySize, DSMEM34);

    float* o0;
    cudaGetSymbolAddress((void**)&o0, g_Opart);

    // One-time infra (no device memory): side stream + capture-legal events.
    static cudaStream_t sB = nullptr;
    static cudaEvent_t eFork = nullptr, eJoin = nullptr;
    if (sB == nullptr) {
        cudaStreamCreateWithFlags(&sB, cudaStreamNonBlocking);
        cudaEventCreateWithFlags(&eFork, cudaEventDisableTiming);
        cudaEventCreateWithFlags(&eJoin, cudaEventDisableTiming);
    }

    // Common prologue on the capture (default) stream.
    convert_x_kernel<<<2048, 256>>>(x);

    // Fork: branch B = convert_w -> stage 3 (tensor-heavy),
    //       branch A (default) = stage 1 -> softmax (light + memory-bound).
    cudaEventRecord(eFork, 0);
    cudaStreamWaitEvent(sB, eFork, 0);

    convert_w_kernel<<<dim3(32, 32, 16), dim3(32, 8), 0, sB>>>(w);
    mma_gemm<3><<<dim3(CC / 128, TT / 128, BB * HH), 256, DSMEM34, sB>>>(nullptr);

    mma_gemm<1><<<dim3(TT / 128, TT / 128, BB * HH), 256, DSMEM1>>>(nullptr);
    softmax_kernel<<<BB * TT * HH, 256>>>();

    // Join: stage 4 needs softmax (A) and Z (B).
    cudaEventRecord(eJoin, sB);
    cudaStreamWaitEvent(0, eJoin, 0);

    mma_gemm<4><<<dim3(CC / 128, TT / 128, BB * NSPLIT), 256, DSMEM34>>>(o0);
    add_out_kernel<<<1024, 256>>>(out);
}

// round 11
// speedup vs baseline: 1.1091x; 1.0261x over previous
#include <cuda_runtime.h>
#include <cuda_fp16.h>
#include <math.h>
#include <stdint.h>

// ---------------------------------------------------------------------------
// Problem constants
// ---------------------------------------------------------------------------
constexpr int BB = 2;
constexpr int TT = 1024;
constexpr int CC = 1024;
constexpr int HH = 16;
constexpr int DD = 64;
constexpr int HT = HH * TT;  // 16384

constexpr int NSPLIT = 8;    // stage-4 head splits (2 heads each)

// ---------------------------------------------------------------------------
// Device scratch
// ---------------------------------------------------------------------------
__device__ float  g_S   [(size_t)BB * TT * HT];     // fp32 scores
__device__ __half g_P   [(size_t)BB * TT * HT];     // softmax probs (fp16)
__device__ __half g_Zt  [(size_t)BB * CC * HT];     // Z^T fp16 [b][e][h*T+s]
__device__ __half g_Xhi [(size_t)BB * TT * CC];     // x hi
__device__ __half g_Xlo [(size_t)BB * TT * CC];     // x lo (scores only)
__device__ __half g_Wt  [(size_t)HH * CC * CC];     // W^T fp16 [h][e][k]
__device__ float  g_Opart[NSPLIT][(size_t)BB * TT * CC]; // stage-4 partials

// ---------------------------------------------------------------------------
// Baseline-PTX helpers (compute_103-safe; no "a"-only features)
// ---------------------------------------------------------------------------
__device__ __forceinline__ uint32_t smem_u32(const void* p) {
    uint32_t a;
    asm("{ .reg .u64 t; cvta.to.shared.u64 t, %1; cvt.u32.u64 %0, t; }" : "=r"(a) : "l"(p));
    return a;
}
__device__ __forceinline__ void cp16(uint32_t saddr, const void* g) {
    asm volatile("cp.async.cg.shared.global [%0], [%1], 16;" :: "r"(saddr), "l"(g));
}
__device__ __forceinline__ void cp_commit() {
    asm volatile("cp.async.commit_group;" ::: "memory");
}
template <int N>
__device__ __forceinline__ void cp_wait() {
    asm volatile("cp.async.wait_group %0;" :: "n"(N) : "memory");
}
#define LDSM4(R, A)                                                               \
    asm volatile("ldmatrix.sync.aligned.m8n8.x4.shared.b16 {%0,%1,%2,%3}, [%4];"  \
                 : "=r"((R)[0]), "=r"((R)[1]), "=r"((R)[2]), "=r"((R)[3]) : "r"(A))

__device__ __forceinline__ void mma_fp16(float* c, const uint32_t* a, const uint32_t* b) {
    asm volatile(
        "mma.sync.aligned.m16n8k16.row.col.f32.f16.f16.f32 "
        "{%0,%1,%2,%3},{%4,%5,%6,%7},{%8,%9},{%0,%1,%2,%3};"
        : "+f"(c[0]), "+f"(c[1]), "+f"(c[2]), "+f"(c[3])
        : "r"(a[0]), "r"(a[1]), "r"(a[2]), "r"(a[3]), "r"(b[0]), "r"(b[1]));
}

// ---------------------------------------------------------------------------
// Conversions
// ---------------------------------------------------------------------------
__global__ void convert_x_kernel(const float* __restrict__ x) {
    size_t n = (size_t)BB * TT * CC;
    for (size_t i = (size_t)blockIdx.x * blockDim.x + threadIdx.x; i < n;
         i += (size_t)gridDim.x * blockDim.x) {
        float f = x[i];
        __half hi = __float2half_rn(f);
        g_Xhi[i] = hi;
        g_Xlo[i] = __float2half_rn(f - __half2float(hi));
    }
}

// W[h*CC + k][e] -> Wt[h][e][k] (single fp16)
__global__ void convert_w_kernel(const float* __restrict__ w) {
    __shared__ float t[32][33];
    int h = blockIdx.z;
    int e0 = blockIdx.x * 32, k0 = blockIdx.y * 32;
    int tx = threadIdx.x, ty = threadIdx.y;  // (32, 8)
#pragma unroll
    for (int r = 0; r < 4; r++) {
        int k = k0 + ty + r * 8;
        t[ty + r * 8][tx] = w[(size_t)(h * CC + k) * CC + e0 + tx];
    }
    __syncthreads();
#pragma unroll
    for (int r = 0; r < 4; r++) {
        int e = e0 + ty + r * 8;
        size_t idx = (size_t)h * CC * CC + (size_t)e * CC + k0 + tx;
        g_Wt[idx] = __float2half_rn(t[tx][ty + r * 8]);
    }
}

// ---------------------------------------------------------------------------
// Softmax: row softmax over s<=t -> fp16 P; only touches s < roundup(t+1,128)
// ---------------------------------------------------------------------------
__global__ __launch_bounds__(256) void softmax_kernel() {
    __shared__ float red[8];
    int row = blockIdx.x;
    int t = (row / HH) & (TT - 1);
    int limit = ((t >> 7) + 1) << 7;  // causal extent rounded to 128
    const float* p = g_S + (size_t)row * TT;
    __half* po = g_P + (size_t)row * TT;
    int tid = threadIdx.x;

    float v[4];
    float m = -INFINITY;
#pragma unroll
    for (int j = 0; j < 4; j++) {
        int s = tid + j * 256;
        if (s <= t) { v[j] = p[s]; m = fmaxf(m, v[j]); }
        else v[j] = -INFINITY;
    }
#pragma unroll
    for (int o = 16; o; o >>= 1) m = fmaxf(m, __shfl_xor_sync(0xffffffffu, m, o));
    if ((tid & 31) == 0) red[tid >> 5] = m;
    __syncthreads();
    if (tid < 32) {
        float mm = (tid < 8) ? red[tid] : -INFINITY;
#pragma unroll
        for (int o = 4; o; o >>= 1) mm = fmaxf(mm, __shfl_xor_sync(0xffffffffu, mm, o));
        if (tid == 0) red[0] = mm;
    }
    __syncthreads();
    m = red[0];
    __syncthreads();

    float sum = 0.0f;
#pragma unroll
    for (int j = 0; j < 4; j++) {
        int s = tid + j * 256;
        if (s <= t) { v[j] = __expf(v[j] - m); sum += v[j]; }
        else v[j] = 0.0f;
    }
#pragma unroll
    for (int o = 16; o; o >>= 1) sum += __shfl_xor_sync(0xffffffffu, sum, o);
    if ((tid & 31) == 0) red[tid >> 5] = sum;
    __syncthreads();
    if (tid < 32) {
        float ss = (tid < 8) ? red[tid] : 0.0f;
#pragma unroll
        for (int o = 4; o; o >>= 1) ss += __shfl_xor_sync(0xffffffffu, ss, o);
        if (tid == 0) red[0] = ss;
    }
    __syncthreads();
    float inv = 1.0f / red[0];

#pragma unroll
    for (int j = 0; j < 4; j++) {
        int s = tid + j * 256;
        if (s < limit) po[s] = __float2half_rn(v[j] * inv);
    }
}

// ---------------------------------------------------------------------------
// HMMA fp16 GEMM template (R8 config). 128x128 tile, K-chunk 32, 4-stage pipe.
// STAGE==1: scores S = Y Y^T (K=64), hi/lo 3-pass, triangular grid,
//           mask-skip stores -> g_S fp32 (masked region never written/read)
// STAGE==3: Z^T = (x @ W_h)^T, single-pass fp16 -> g_Zt fp16
// STAGE==4: out = P @ Z, 8-way head split + LPT -> g_Opart
// ---------------------------------------------------------------------------
constexpr int TSTRIDE = 80;               // padded smem row (bytes)
constexpr int TILE_B = 128 * TSTRIDE;     // 10240
constexpr int NBUF = 4;

template <int STAGE>
__global__ __launch_bounds__(256, 1) void mma_gemm(float* __restrict__ Out) {
    constexpr int NA = (STAGE == 1) ? 2 : 1;   // # A tiles (hi[,lo])
    constexpr int NB = (STAGE == 1) ? 2 : 1;   // # B tiles (hi[,lo])
    constexpr int BUF_B = (NA + NB) * TILE_B;

    extern __shared__ char sp[];
    const uint32_t sbase = smem_u32(sp);

    const int tid = threadIdx.x;
    const int lane = tid & 31;
    const int wid = tid >> 5;
    const int wm = wid & 3;      // 4 warps along M (32 rows each)
    const int wn = wid >> 2;     // 2 warps along N (64 cols each)

    int m0, n0;
    if (STAGE == 1) {
        // triangular packing: blockIdx.x in [0,36) -> (tx <= ty)
        int i = blockIdx.x;
        int ty = (int)((sqrtf(8.0f * (float)i + 1.0f) - 1.0f) * 0.5f);
        while ((ty + 1) * (ty + 2) / 2 <= i) ty++;
        while (ty * (ty + 1) / 2 > i) ty--;
        int tx = i - ty * (ty + 1) / 2;
        m0 = ty * 128; n0 = tx * 128;
    } else if (STAGE == 4) {
        // LPT: heavy tiles (large by) first
        m0 = (gridDim.y - 1 - blockIdx.y) * 128; n0 = blockIdx.x * 128;
    } else {
        m0 = blockIdx.y * 128; n0 = blockIdx.x * 128;
    }
    const int by = m0 >> 7;

    int b, h = 0, part = 0;
    const __half *A0, *A1 = nullptr, *B0, *B1 = nullptr;
    size_t ldA, ldB;
    int NC, kph = 0;
    if (STAGE == 1) {
        int z = blockIdx.z; b = z >> 4; h = z & 15;
        A0 = g_Xhi + (size_t)b * TT * CC + h * DD;
        A1 = g_Xlo + (size_t)b * TT * CC + h * DD;
        B0 = A0; B1 = A1; ldA = CC; ldB = CC;
        NC = 2;
    } else if (STAGE == 3) {
        int z = blockIdx.z; b = z >> 4; h = z & 15;
        A0 = g_Xhi + (size_t)b * TT * CC; ldA = CC;
        B0 = g_Wt + (size_t)h * CC * CC; ldB = CC;
        NC = 32;
    } else {
        int z = blockIdx.z; b = z / NSPLIT; part = z % NSPLIT;
        A0 = g_P + (size_t)b * TT * HT; ldA = HT;
        B0 = g_Zt + (size_t)b * CC * HT; ldB = HT;
        kph = (by + 1) * 4;                // kept 32-chunks per head (causal)
        NC = (HH / NSPLIT) * kph;          // 2 heads per split
    }

    auto kk_of = [&](int i) -> int {
        if (STAGE == 4) return (part * (HH / NSPLIT) + i / kph) * TT + (i % kph) * 32;
        return i * 32;
    };

    const int lr = tid >> 1;
    const int lc = (tid & 1) * 2;
    auto load_tiles = [&](int i, int buf) {
        int kk = kk_of(i);
        uint32_t sb = sbase + buf * BUF_B + lr * TSTRIDE + lc * 16;
        size_t offA = (size_t)(m0 + lr) * ldA + kk + lc * 8;
        size_t offB = (size_t)(n0 + lr) * ldB + kk + lc * 8;
        cp16(sb, A0 + offA);
        cp16(sb + 16, A0 + offA + 8);
        if (NA == 2) {
            cp16(sb + TILE_B, A1 + offA);
            cp16(sb + TILE_B + 16, A1 + offA + 8);
        }
        cp16(sb + NA * TILE_B, B0 + offB);
        cp16(sb + NA * TILE_B + 16, B0 + offB + 8);
        if (NB == 2) {
            cp16(sb + (NA + 1) * TILE_B, B1 + offB);
            cp16(sb + (NA + 1) * TILE_B + 16, B1 + offB + 8);
        }
    };

    float acc[2][8][4];
#pragma unroll
    for (int i = 0; i < 2; i++)
#pragma unroll
        for (int j = 0; j < 8; j++)
#pragma unroll
            for (int k = 0; k < 4; k++) acc[i][j][k] = 0.0f;

    // prologue: always NBUF-1 committed groups (empty groups complete trivially)
#pragma unroll
    for (int j = 0; j < NBUF - 1; j++) {
        if (j < NC) load_tiles(j, j);
        cp_commit();
    }

    for (int i = 0; i < NC; ++i) {
        cp_wait<NBUF - 2>();
        __syncthreads();

        const uint32_t base = sbase + (i & (NBUF - 1)) * BUF_B;
#pragma unroll
        for (int ks = 0; ks < 2; ks++) {
            uint32_t afr[NA][2][4], bfr[NB][4][4];
#pragma unroll
            for (int mt = 0; mt < 2; mt++) {
                uint32_t a = base + (uint32_t)(wm * 32 + mt * 16 + (lane & 15)) * TSTRIDE
                             + ((lane >> 4) << 4) + ks * 32;
                LDSM4(afr[0][mt], a);
                if (NA == 2) LDSM4(afr[1][mt], a + TILE_B);
            }
#pragma unroll
            for (int q = 0; q < 4; q++) {
                uint32_t a = base + NA * TILE_B
                             + (uint32_t)(wn * 64 + q * 16 + ((lane >> 4) << 3) + (lane & 7)) * TSTRIDE
                             + (((lane >> 3) & 1) << 4) + ks * 32;
                LDSM4(bfr[0][q], a);
                if (NB == 2) LDSM4(bfr[1][q], a + TILE_B);
            }
            // compensation passes: skip lo*lo
#pragma unroll
            for (int ia = 0; ia < NA; ia++)
#pragma unroll
                for (int ib = 0; ib < NB; ib++) {
                    if (ia + ib == 2) continue;
#pragma unroll
                    for (int mt = 0; mt < 2; mt++)
#pragma unroll
                        for (int q = 0; q < 4; q++) {
                            mma_fp16(acc[mt][2 * q],     afr[ia][mt], &bfr[ib][q][0]);
                            mma_fp16(acc[mt][2 * q + 1], afr[ia][mt], &bfr[ib][q][2]);
                        }
                }
        }
        if (i + NBUF - 1 < NC) load_tiles(i + NBUF - 1, (i + NBUF - 1) & (NBUF - 1));
        cp_commit();
    }
    cp_wait<0>();
    __syncthreads();

    if (STAGE == 1) {
        int z = blockIdx.z;
        float* Cp = g_S + (size_t)(z >> 4) * TT * HT + (size_t)(z & 15) * TT;
#pragma unroll
        for (int mt = 0; mt < 2; mt++)
#pragma unroll
            for (int nt = 0; nt < 8; nt++)
#pragma unroll
                for (int ci = 0; ci < 4; ci++) {
                    int row = m0 + wm * 32 + mt * 16 + (lane >> 2) + (ci >> 1) * 8;
                    int col = n0 + wn * 64 + nt * 8 + ((lane & 3) << 1) + (ci & 1);
                    if (col <= row)  // masked region never read by softmax
                        Cp[(size_t)row * HT + col] = acc[mt][nt][ci] * 0.25f;
                }
    } else if (STAGE == 4) {
        float* ob = Out + ((size_t)part * BB + b) * TT * CC;
#pragma unroll
        for (int mt = 0; mt < 2; mt++)
#pragma unroll
            for (int nt = 0; nt < 8; nt++) {
                int row = m0 + wm * 32 + mt * 16 + (lane >> 2);
                int col = n0 + wn * 64 + nt * 8 + ((lane & 3) << 1);
                *reinterpret_cast<float2*>(&ob[(size_t)row * CC + col]) =
                    make_float2(acc[mt][nt][0], acc[mt][nt][1]);
                *reinterpret_cast<float2*>(&ob[(size_t)(row + 8) * CC + col]) =
                    make_float2(acc[mt][nt][2], acc[mt][nt][3]);
            }
    } else {
        // STAGE 3: transpose through smem, then coalesced Z^T fp16 stores
        constexpr int TROW = 272;             // 128*2 + 16 pad
#pragma unroll
        for (int mt = 0; mt < 2; mt++)
#pragma unroll
            for (int nt = 0; nt < 8; nt++)
#pragma unroll
                for (int ci = 0; ci < 4; ci++) {
                    int row = wm * 32 + mt * 16 + (lane >> 2) + (ci >> 1) * 8;  // m
                    int col = wn * 64 + nt * 8 + ((lane & 3) << 1) + (ci & 1);  // e
                    *reinterpret_cast<__half*>(sp + col * TROW + row * 2) =
                        __float2half_rn(acc[mt][nt][ci]);
                }
        __syncthreads();
        size_t gb = (size_t)b * CC * HT + (size_t)h * TT + m0;
        for (int idx = tid; idx < 128 * 16; idx += 256) {
            int r = idx >> 4, cch = idx & 15;
            uint4 v = *reinterpret_cast<uint4*>(sp + r * TROW + cch * 16);
            *reinterpret_cast<uint4*>(&g_Zt[gb + (size_t)(n0 + r) * HT + cch * 8]) = v;
        }
    }
}

// ---------------------------------------------------------------------------
// Sum the eight stage-4 head-split partials into the final output.
// ---------------------------------------------------------------------------
__global__ void add_out_kernel(float* __restrict__ out) {
    size_t n = (size_t)BB * TT * CC / 4;
    float4* o = reinterpret_cast<float4*>(out);
    for (size_t i = (size_t)blockIdx.x * blockDim.x + threadIdx.x; i < n;
         i += (size_t)gridDim.x * blockDim.x) {
        float x = 0, y = 0, z = 0, w = 0;
#pragma unroll
        for (int p = 0; p < NSPLIT; p++) {
            float4 v = reinterpret_cast<const float4*>(g_Opart[p])[i];
            x += v.x; y += v.y; z += v.z; w += v.w;
        }
        o[i] = make_float4(x, y, z, w);
    }
}

// ---------------------------------------------------------------------------
extern "C" void kernel_launch(void* const* d_in, const int* in_sizes, int n_in,
                              void* d_out, int out_size) {
    const float* x = (const float*)d_in[0];
    // d_in[1]: boolean causal mask == triu(k=1); applied analytically in-kernel.
    const float* w = (const float*)d_in[2];
    float* out = (float*)d_out;

    constexpr int DSMEM1 = NBUF * 4 * TILE_B;  // 163840 (NA=2, NB=2)
    constexpr int DSMEM34 = NBUF * 2 * TILE_B; // 81920  (NA=1, NB=1)

    cudaFuncSetAttribute(mma_gemm<1>, cudaFuncAttributeMaxDynamicSharedMemorySize, DSMEM1);
    cudaFuncSetAttribute(mma_gemm<3>, cudaFuncAttributeMaxDynamicSharedMemorySize, DSMEM34);
    cudaFuncSetAttribute(mma_gemm<4>, cudaFuncAttributeMaxDynamicSharedMemorySize, DSMEM34);

    float* o0;
    cudaGetSymbolAddress((void**)&o0, g_Opart);

    // One-time infra (no device memory): side stream + capture-legal events.
    static cudaStream_t sB = nullptr;
    static cudaEvent_t eFork = nullptr, eX = nullptr, eJoin = nullptr;
    if (sB == nullptr) {
        cudaStreamCreateWithFlags(&sB, cudaStreamNonBlocking);
        cudaEventCreateWithFlags(&eFork, cudaEventDisableTiming);
        cudaEventCreateWithFlags(&eX, cudaEventDisableTiming);
        cudaEventCreateWithFlags(&eJoin, cudaEventDisableTiming);
    }

    // Fork immediately: branch B starts convert_w (depends only on w)
    // in parallel with convert_x on the capture stream.
    cudaEventRecord(eFork, 0);
    cudaStreamWaitEvent(sB, eFork, 0);
    convert_w_kernel<<<dim3(32, 32, 16), dim3(32, 8), 0, sB>>>(w);

    convert_x_kernel<<<2048, 256>>>(x);
    cudaEventRecord(eX, 0);

    // Branch B: stage 3 (needs convert_x + convert_w).
    cudaStreamWaitEvent(sB, eX, 0);
    mma_gemm<3><<<dim3(CC / 128, TT / 128, BB * HH), 256, DSMEM34, sB>>>(nullptr);

    // Branch A: stage 1 (triangular grid) -> softmax.
    mma_gemm<1><<<dim3(36, 1, BB * HH), 256, DSMEM1>>>(nullptr);
    softmax_kernel<<<BB * TT * HH, 256>>>();

    // Join: stage 4 needs softmax (A) and Z (B).
    cudaEventRecord(eJoin, sB);
    cudaStreamWaitEvent(0, eJoin, 0);

    mma_gemm<4><<<dim3(CC / 128, TT / 128, BB * NSPLIT), 256, DSMEM34>>>(o0);
    add_out_kernel<<<1024, 256>>>(out);
}

// round 12
// speedup vs baseline: 1.1171x; 1.0072x over previous
#include <cuda_runtime.h>
#include <cuda_fp16.h>
#include <math.h>
#include <stdint.h>

// ---------------------------------------------------------------------------
// Problem constants
// ---------------------------------------------------------------------------
constexpr int BB = 2;
constexpr int TT = 1024;
constexpr int CC = 1024;
constexpr int HH = 16;
constexpr int DD = 64;
constexpr int HT = HH * TT;  // 16384

constexpr int NSPLIT = 8;    // stage-4 head splits (2 heads each)

// ---------------------------------------------------------------------------
// Device scratch
// ---------------------------------------------------------------------------
__device__ float  g_S   [(size_t)BB * TT * HT];     // fp32 scores
__device__ __half g_P   [(size_t)BB * TT * HT];     // softmax probs (fp16)
__device__ __half g_Zt  [(size_t)BB * CC * HT];     // Z^T fp16 [b][e][h*T+s]
__device__ __half g_Xhi [(size_t)BB * TT * CC];     // x hi
__device__ __half g_Xlo [(size_t)BB * TT * CC];     // x lo (scores only)
__device__ __half g_Wt  [(size_t)HH * CC * CC];     // W^T fp16 [h][e][k]
__device__ float  g_Opart[NSPLIT][(size_t)BB * TT * CC]; // stage-4 partials

// ---------------------------------------------------------------------------
// Baseline-PTX helpers (compute_103-safe; no "a"-only features)
// ---------------------------------------------------------------------------
__device__ __forceinline__ uint32_t smem_u32(const void* p) {
    uint32_t a;
    asm("{ .reg .u64 t; cvta.to.shared.u64 t, %1; cvt.u32.u64 %0, t; }" : "=r"(a) : "l"(p));
    return a;
}
__device__ __forceinline__ void cp16(uint32_t saddr, const void* g) {
    asm volatile("cp.async.cg.shared.global [%0], [%1], 16;" :: "r"(saddr), "l"(g));
}
__device__ __forceinline__ void cp_commit() {
    asm volatile("cp.async.commit_group;" ::: "memory");
}
template <int N>
__device__ __forceinline__ void cp_wait() {
    asm volatile("cp.async.wait_group %0;" :: "n"(N) : "memory");
}
#define LDSM4(R, A)                                                               \
    asm volatile("ldmatrix.sync.aligned.m8n8.x4.shared.b16 {%0,%1,%2,%3}, [%4];"  \
                 : "=r"((R)[0]), "=r"((R)[1]), "=r"((R)[2]), "=r"((R)[3]) : "r"(A))

__device__ __forceinline__ void mma_fp16(float* c, const uint32_t* a, const uint32_t* b) {
    asm volatile(
        "mma.sync.aligned.m16n8k16.row.col.f32.f16.f16.f32 "
        "{%0,%1,%2,%3},{%4,%5,%6,%7},{%8,%9},{%0,%1,%2,%3};"
        : "+f"(c[0]), "+f"(c[1]), "+f"(c[2]), "+f"(c[3])
        : "r"(a[0]), "r"(a[1]), "r"(a[2]), "r"(a[3]), "r"(b[0]), "r"(b[1]));
}

// ---------------------------------------------------------------------------
// Conversions
// ---------------------------------------------------------------------------
__global__ void convert_x_kernel(const float* __restrict__ x) {
    size_t n = (size_t)BB * TT * CC;
    for (size_t i = (size_t)blockIdx.x * blockDim.x + threadIdx.x; i < n;
         i += (size_t)gridDim.x * blockDim.x) {
        float f = x[i];
        __half hi = __float2half_rn(f);
        g_Xhi[i] = hi;
        g_Xlo[i] = __float2half_rn(f - __half2float(hi));
    }
}

// W[h*CC + k][e] -> Wt[h][e][k] (single fp16)
__global__ void convert_w_kernel(const float* __restrict__ w) {
    __shared__ float t[32][33];
    int h = blockIdx.z;
    int e0 = blockIdx.x * 32, k0 = blockIdx.y * 32;
    int tx = threadIdx.x, ty = threadIdx.y;  // (32, 8)
#pragma unroll
    for (int r = 0; r < 4; r++) {
        int k = k0 + ty + r * 8;
        t[ty + r * 8][tx] = w[(size_t)(h * CC + k) * CC + e0 + tx];
    }
    __syncthreads();
#pragma unroll
    for (int r = 0; r < 4; r++) {
        int e = e0 + ty + r * 8;
        size_t idx = (size_t)h * CC * CC + (size_t)e * CC + k0 + tx;
        g_Wt[idx] = __float2half_rn(t[tx][ty + r * 8]);
    }
}

// ---------------------------------------------------------------------------
// Softmax: row softmax over s<=t -> fp16 P; only touches s < roundup(t+1,128)
// ---------------------------------------------------------------------------
__global__ __launch_bounds__(256) void softmax_kernel() {
    __shared__ float red[8];
    int row = blockIdx.x;
    int t = (row / HH) & (TT - 1);
    int limit = ((t >> 7) + 1) << 7;  // causal extent rounded to 128
    const float* p = g_S + (size_t)row * TT;
    __half* po = g_P + (size_t)row * TT;
    int tid = threadIdx.x;

    float v[4];
    float m = -INFINITY;
#pragma unroll
    for (int j = 0; j < 4; j++) {
        int s = tid + j * 256;
        if (s <= t) { v[j] = p[s]; m = fmaxf(m, v[j]); }
        else v[j] = -INFINITY;
    }
#pragma unroll
    for (int o = 16; o; o >>= 1) m = fmaxf(m, __shfl_xor_sync(0xffffffffu, m, o));
    if ((tid & 31) == 0) red[tid >> 5] = m;
    __syncthreads();
    if (tid < 32) {
        float mm = (tid < 8) ? red[tid] : -INFINITY;
#pragma unroll
        for (int o = 4; o; o >>= 1) mm = fmaxf(mm, __shfl_xor_sync(0xffffffffu, mm, o));
        if (tid == 0) red[0] = mm;
    }
    __syncthreads();
    m = red[0];
    __syncthreads();

    float sum = 0.0f;
#pragma unroll
    for (int j = 0; j < 4; j++) {
        int s = tid + j * 256;
        if (s <= t) { v[j] = __expf(v[j] - m); sum += v[j]; }
        else v[j] = 0.0f;
    }
#pragma unroll
    for (int o = 16; o; o >>= 1) sum += __shfl_xor_sync(0xffffffffu, sum, o);
    if ((tid & 31) == 0) red[tid >> 5] = sum;
    __syncthreads();
    if (tid < 32) {
        float ss = (tid < 8) ? red[tid] : 0.0f;
#pragma unroll
        for (int o = 4; o; o >>= 1) ss += __shfl_xor_sync(0xffffffffu, ss, o);
        if (tid == 0) red[0] = ss;
    }
    __syncthreads();
    float inv = 1.0f / red[0];

#pragma unroll
    for (int j = 0; j < 4; j++) {
        int s = tid + j * 256;
        if (s < limit) po[s] = __float2half_rn(v[j] * inv);
    }
}

// ---------------------------------------------------------------------------
// HMMA fp16 GEMM template (R8 config). 128x128 tile, K-chunk 32, 4-stage pipe.
// STAGE==1: scores S = Y Y^T (K=64), hi/lo 3-pass, triangular grid,
//           mask-skip stores -> g_S fp32
// STAGE==3: Z^T = (x @ W_h)^T, single-pass fp16, heads zoff..zoff+7 -> g_Zt
// STAGE==4: out = P @ Z, parts zoff..zoff+3 (2 heads each) + LPT -> g_Opart
// ---------------------------------------------------------------------------
constexpr int TSTRIDE = 80;               // padded smem row (bytes)
constexpr int TILE_B = 128 * TSTRIDE;     // 10240
constexpr int NBUF = 4;

template <int STAGE>
__global__ __launch_bounds__(256, 1) void mma_gemm(float* __restrict__ Out, int zoff) {
    constexpr int NA = (STAGE == 1) ? 2 : 1;   // # A tiles (hi[,lo])
    constexpr int NB = (STAGE == 1) ? 2 : 1;   // # B tiles (hi[,lo])
    constexpr int BUF_B = (NA + NB) * TILE_B;

    extern __shared__ char sp[];
    const uint32_t sbase = smem_u32(sp);

    const int tid = threadIdx.x;
    const int lane = tid & 31;
    const int wid = tid >> 5;
    const int wm = wid & 3;      // 4 warps along M (32 rows each)
    const int wn = wid >> 2;     // 2 warps along N (64 cols each)

    int m0, n0;
    if (STAGE == 1) {
        // triangular packing: blockIdx.x in [0,36) -> (tx <= ty)
        int i = blockIdx.x;
        int ty = (int)((sqrtf(8.0f * (float)i + 1.0f) - 1.0f) * 0.5f);
        while ((ty + 1) * (ty + 2) / 2 <= i) ty++;
        while (ty * (ty + 1) / 2 > i) ty--;
        int tx = i - ty * (ty + 1) / 2;
        m0 = ty * 128; n0 = tx * 128;
    } else if (STAGE == 4) {
        // LPT: heavy tiles (large by) first
        m0 = (gridDim.y - 1 - blockIdx.y) * 128; n0 = blockIdx.x * 128;
    } else {
        m0 = blockIdx.y * 128; n0 = blockIdx.x * 128;
    }
    const int by = m0 >> 7;

    int b, h = 0, part = 0;
    const __half *A0, *A1 = nullptr, *B0, *B1 = nullptr;
    size_t ldA, ldB;
    int NC, kph = 0;
    if (STAGE == 1) {
        int z = blockIdx.z; b = z >> 4; h = z & 15;
        A0 = g_Xhi + (size_t)b * TT * CC + h * DD;
        A1 = g_Xlo + (size_t)b * TT * CC + h * DD;
        B0 = A0; B1 = A1; ldA = CC; ldB = CC;
        NC = 2;
    } else if (STAGE == 3) {
        int z = blockIdx.z; b = z >> 3; h = zoff + (z & 7);   // 8 heads per launch
        A0 = g_Xhi + (size_t)b * TT * CC; ldA = CC;
        B0 = g_Wt + (size_t)h * CC * CC; ldB = CC;
        NC = 32;
    } else {
        int z = blockIdx.z; b = z >> 2; part = zoff + (z & 3); // 4 parts per launch
        A0 = g_P + (size_t)b * TT * HT; ldA = HT;
        B0 = g_Zt + (size_t)b * CC * HT; ldB = HT;
        kph = (by + 1) * 4;                // kept 32-chunks per head (causal)
        NC = (HH / NSPLIT) * kph;          // 2 heads per part
    }

    auto kk_of = [&](int i) -> int {
        if (STAGE == 4) return (part * (HH / NSPLIT) + i / kph) * TT + (i % kph) * 32;
        return i * 32;
    };

    const int lr = tid >> 1;
    const int lc = (tid & 1) * 2;
    auto load_tiles = [&](int i, int buf) {
        int kk = kk_of(i);
        uint32_t sb = sbase + buf * BUF_B + lr * TSTRIDE + lc * 16;
        size_t offA = (size_t)(m0 + lr) * ldA + kk + lc * 8;
        size_t offB = (size_t)(n0 + lr) * ldB + kk + lc * 8;
        cp16(sb, A0 + offA);
        cp16(sb + 16, A0 + offA + 8);
        if (NA == 2) {
            cp16(sb + TILE_B, A1 + offA);
            cp16(sb + TILE_B + 16, A1 + offA + 8);
        }
        cp16(sb + NA * TILE_B, B0 + offB);
        cp16(sb + NA * TILE_B + 16, B0 + offB + 8);
        if (NB == 2) {
            cp16(sb + (NA + 1) * TILE_B, B1 + offB);
            cp16(sb + (NA + 1) * TILE_B + 16, B1 + offB + 8);
        }
    };

    float acc[2][8][4];
#pragma unroll
    for (int i = 0; i < 2; i++)
#pragma unroll
        for (int j = 0; j < 8; j++)
#pragma unroll
            for (int k = 0; k < 4; k++) acc[i][j][k] = 0.0f;

    // prologue: always NBUF-1 committed groups (empty groups complete trivially)
#pragma unroll
    for (int j = 0; j < NBUF - 1; j++) {
        if (j < NC) load_tiles(j, j);
        cp_commit();
    }

    for (int i = 0; i < NC; ++i) {
        cp_wait<NBUF - 2>();
        __syncthreads();

        const uint32_t base = sbase + (i & (NBUF - 1)) * BUF_B;
#pragma unroll
        for (int ks = 0; ks < 2; ks++) {
            uint32_t afr[NA][2][4], bfr[NB][4][4];
#pragma unroll
            for (int mt = 0; mt < 2; mt++) {
                uint32_t a = base + (uint32_t)(wm * 32 + mt * 16 + (lane & 15)) * TSTRIDE
                             + ((lane >> 4) << 4) + ks * 32;
                LDSM4(afr[0][mt], a);
                if (NA == 2) LDSM4(afr[1][mt], a + TILE_B);
            }
#pragma unroll
            for (int q = 0; q < 4; q++) {
                uint32_t a = base + NA * TILE_B
                             + (uint32_t)(wn * 64 + q * 16 + ((lane >> 4) << 3) + (lane & 7)) * TSTRIDE
                             + (((lane >> 3) & 1) << 4) + ks * 32;
                LDSM4(bfr[0][q], a);
                if (NB == 2) LDSM4(bfr[1][q], a + TILE_B);
            }
            // compensation passes: skip lo*lo
#pragma unroll
            for (int ia = 0; ia < NA; ia++)
#pragma unroll
                for (int ib = 0; ib < NB; ib++) {
                    if (ia + ib == 2) continue;
#pragma unroll
                    for (int mt = 0; mt < 2; mt++)
#pragma unroll
                        for (int q = 0; q < 4; q++) {
                            mma_fp16(acc[mt][2 * q],     afr[ia][mt], &bfr[ib][q][0]);
                            mma_fp16(acc[mt][2 * q + 1], afr[ia][mt], &bfr[ib][q][2]);
                        }
                }
        }
        if (i + NBUF - 1 < NC) load_tiles(i + NBUF - 1, (i + NBUF - 1) & (NBUF - 1));
        cp_commit();
    }
    cp_wait<0>();
    __syncthreads();

    if (STAGE == 1) {
        int z = blockIdx.z;
        float* Cp = g_S + (size_t)(z >> 4) * TT * HT + (size_t)(z & 15) * TT;
#pragma unroll
        for (int mt = 0; mt < 2; mt++)
#pragma unroll
            for (int nt = 0; nt < 8; nt++)
#pragma unroll
                for (int ci = 0; ci < 4; ci++) {
                    int row = m0 + wm * 32 + mt * 16 + (lane >> 2) + (ci >> 1) * 8;
                    int col = n0 + wn * 64 + nt * 8 + ((lane & 3) << 1) + (ci & 1);
                    if (col <= row)  // masked region never read by softmax
                        Cp[(size_t)row * HT + col] = acc[mt][nt][ci] * 0.25f;
                }
    } else if (STAGE == 4) {
        float* ob = Out + ((size_t)part * BB + b) * TT * CC;
#pragma unroll
        for (int mt = 0; mt < 2; mt++)
#pragma unroll
            for (int nt = 0; nt < 8; nt++) {
                int row = m0 + wm * 32 + mt * 16 + (lane >> 2);
                int col = n0 + wn * 64 + nt * 8 + ((lane & 3) << 1);
                *reinterpret_cast<float2*>(&ob[(size_t)row * CC + col]) =
                    make_float2(acc[mt][nt][0], acc[mt][nt][1]);
                *reinterpret_cast<float2*>(&ob[(size_t)(row + 8) * CC + col]) =
                    make_float2(acc[mt][nt][2], acc[mt][nt][3]);
            }
    } else {
        // STAGE 3: transpose through smem, then coalesced Z^T fp16 stores
        constexpr int TROW = 272;             // 128*2 + 16 pad
#pragma unroll
        for (int mt = 0; mt < 2; mt++)
#pragma unroll
            for (int nt = 0; nt < 8; nt++)
#pragma unroll
                for (int ci = 0; ci < 4; ci++) {
                    int row = wm * 32 + mt * 16 + (lane >> 2) + (ci >> 1) * 8;  // m
                    int col = wn * 64 + nt * 8 + ((lane & 3) << 1) + (ci & 1);  // e
                    *reinterpret_cast<__half*>(sp + col * TROW + row * 2) =
                        __float2half_rn(acc[mt][nt][ci]);
                }
        __syncthreads();
        size_t gb = (size_t)b * CC * HT + (size_t)h * TT + m0;
        for (int idx = tid; idx < 128 * 16; idx += 256) {
            int r = idx >> 4, cch = idx & 15;
            uint4 v = *reinterpret_cast<uint4*>(sp + r * TROW + cch * 16);
            *reinterpret_cast<uint4*>(&g_Zt[gb + (size_t)(n0 + r) * HT + cch * 8]) = v;
        }
    }
}

// ---------------------------------------------------------------------------
// Sum the eight stage-4 head-split partials into the final output.
// ---------------------------------------------------------------------------
__global__ void add_out_kernel(float* __restrict__ out) {
    size_t n = (size_t)BB * TT * CC / 4;
    float4* o = reinterpret_cast<float4*>(out);
    for (size_t i = (size_t)blockIdx.x * blockDim.x + threadIdx.x; i < n;
         i += (size_t)gridDim.x * blockDim.x) {
        float x = 0, y = 0, z = 0, w = 0;
#pragma unroll
        for (int p = 0; p < NSPLIT; p++) {
            float4 v = reinterpret_cast<const float4*>(g_Opart[p])[i];
            x += v.x; y += v.y; z += v.z; w += v.w;
        }
        o[i] = make_float4(x, y, z, w);
    }
}

// ---------------------------------------------------------------------------
extern "C" void kernel_launch(void* const* d_in, const int* in_sizes, int n_in,
                              void* d_out, int out_size) {
    const float* x = (const float*)d_in[0];
    // d_in[1]: boolean causal mask == triu(k=1); applied analytically in-kernel.
    const float* w = (const float*)d_in[2];
    float* out = (float*)d_out;

    constexpr int DSMEM1 = NBUF * 4 * TILE_B;  // 163840 (NA=2, NB=2)
    constexpr int DSMEM34 = NBUF * 2 * TILE_B; // 81920  (NA=1, NB=1)

    cudaFuncSetAttribute(mma_gemm<1>, cudaFuncAttributeMaxDynamicSharedMemorySize, DSMEM1);
    cudaFuncSetAttribute(mma_gemm<3>, cudaFuncAttributeMaxDynamicSharedMemorySize, DSMEM34);
    cudaFuncSetAttribute(mma_gemm<4>, cudaFuncAttributeMaxDynamicSharedMemorySize, DSMEM34);

    float* o0;
    cudaGetSymbolAddress((void**)&o0, g_Opart);

    // One-time infra (no device memory): side stream + capture-legal events.
    static cudaStream_t sB = nullptr;
    static cudaEvent_t eFork = nullptr, eX = nullptr, eP = nullptr;
    static cudaEvent_t e3a = nullptr, eJoin = nullptr;
    if (sB == nullptr) {
        cudaStreamCreateWithFlags(&sB, cudaStreamNonBlocking);
        cudaEventCreateWithFlags(&eFork, cudaEventDisableTiming);
        cudaEventCreateWithFlags(&eX, cudaEventDisableTiming);
        cudaEventCreateWithFlags(&eP, cudaEventDisableTiming);
        cudaEventCreateWithFlags(&e3a, cudaEventDisableTiming);
        cudaEventCreateWithFlags(&eJoin, cudaEventDisableTiming);
    }

    // Fork immediately: branch B starts convert_w (depends only on w).
    cudaEventRecord(eFork, 0);
    cudaStreamWaitEvent(sB, eFork, 0);
    convert_w_kernel<<<dim3(32, 32, 16), dim3(32, 8), 0, sB>>>(w);

    convert_x_kernel<<<2048, 256>>>(x);
    cudaEventRecord(eX, 0);

    // Branch B: stage 3 in two head-halves.
    cudaStreamWaitEvent(sB, eX, 0);
    mma_gemm<3><<<dim3(CC / 128, TT / 128, BB * 8), 256, DSMEM34, sB>>>(nullptr, 0);
    cudaEventRecord(e3a, sB);
    mma_gemm<3><<<dim3(CC / 128, TT / 128, BB * 8), 256, DSMEM34, sB>>>(nullptr, 8);

    // Branch A: stage 1 (triangular grid) -> softmax.
    mma_gemm<1><<<dim3(36, 1, BB * HH), 256, DSMEM1>>>(nullptr, 0);
    softmax_kernel<<<BB * TT * HH, 256>>>();
    cudaEventRecord(eP, 0);

    // Stage 4 half 1 (heads 0-7) on main stream: needs softmax + e3a.
    cudaStreamWaitEvent(0, e3a, 0);
    mma_gemm<4><<<dim3(CC / 128, TT / 128, BB * 4), 256, DSMEM34>>>(o0, 0);

    // Stage 4 half 2 (heads 8-15) on side stream: needs stage3 half 2 + softmax.
    cudaStreamWaitEvent(sB, eP, 0);
    mma_gemm<4><<<dim3(CC / 128, TT / 128, BB * 4), 256, DSMEM34, sB>>>(o0, 4);
    cudaEventRecord(eJoin, sB);

    // Final sum after both halves.
    cudaStreamWaitEvent(0, eJoin, 0);
    add_out_kernel<<<1024, 256>>>(out);
}

// round 13
// speedup vs baseline: 1.2695x; 1.1364x over previous
#include <cuda_runtime.h>
#include <cuda_fp16.h>
#include <math.h>
#include <stdint.h>

// ---------------------------------------------------------------------------
// Problem constants
// ---------------------------------------------------------------------------
constexpr int BB = 2;
constexpr int TT = 1024;
constexpr int CC = 1024;
constexpr int HH = 16;
constexpr int DD = 64;
constexpr int HT = HH * TT;  // 16384

constexpr int NSPLIT = 8;    // stage-4 head splits (2 heads each)

// ---------------------------------------------------------------------------
// Device scratch
// ---------------------------------------------------------------------------
__device__ float  g_S   [(size_t)BB * TT * HT];     // fp32 scores
__device__ __half g_P   [(size_t)BB * TT * HT];     // softmax probs (fp16)
__device__ __half g_Zt  [(size_t)BB * CC * HT];     // Z^T fp16 [b][e][h*T+s]
__device__ __half g_Xhi [(size_t)BB * TT * CC];     // x hi
__device__ __half g_Xlo [(size_t)BB * TT * CC];     // x lo (scores only)
__device__ __half g_Wt  [(size_t)HH * CC * CC];     // W^T fp16 [h][e][k]
__device__ float  g_Opart[NSPLIT][(size_t)BB * TT * CC]; // stage-4 partials

// ---------------------------------------------------------------------------
// Baseline-PTX helpers (compute_103-safe; no "a"-only features)
// ---------------------------------------------------------------------------
__device__ __forceinline__ uint32_t smem_u32(const void* p) {
    uint32_t a;
    asm("{ .reg .u64 t; cvta.to.shared.u64 t, %1; cvt.u32.u64 %0, t; }" : "=r"(a) : "l"(p));
    return a;
}
__device__ __forceinline__ void cp16(uint32_t saddr, const void* g) {
    asm volatile("cp.async.cg.shared.global [%0], [%1], 16;" :: "r"(saddr), "l"(g));
}
__device__ __forceinline__ void cp_commit() {
    asm volatile("cp.async.commit_group;" ::: "memory");
}
template <int N>
__device__ __forceinline__ void cp_wait() {
    asm volatile("cp.async.wait_group %0;" :: "n"(N) : "memory");
}
#define LDSM4(R, A)                                                               \
    asm volatile("ldmatrix.sync.aligned.m8n8.x4.shared.b16 {%0,%1,%2,%3}, [%4];"  \
                 : "=r"((R)[0]), "=r"((R)[1]), "=r"((R)[2]), "=r"((R)[3]) : "r"(A))

__device__ __forceinline__ void mma_fp16(float* c, const uint32_t* a, const uint32_t* b) {
    asm volatile(
        "mma.sync.aligned.m16n8k16.row.col.f32.f16.f16.f32 "
        "{%0,%1,%2,%3},{%4,%5,%6,%7},{%8,%9},{%0,%1,%2,%3};"
        : "+f"(c[0]), "+f"(c[1]), "+f"(c[2]), "+f"(c[3])
        : "r"(a[0]), "r"(a[1]), "r"(a[2]), "r"(a[3]), "r"(b[0]), "r"(b[1]));
}

// ---------------------------------------------------------------------------
// Conversions
// ---------------------------------------------------------------------------
__global__ void convert_x_kernel(const float* __restrict__ x) {
    size_t n = (size_t)BB * TT * CC;
    for (size_t i = (size_t)blockIdx.x * blockDim.x + threadIdx.x; i < n;
         i += (size_t)gridDim.x * blockDim.x) {
        float f = x[i];
        __half hi = __float2half_rn(f);
        g_Xhi[i] = hi;
        g_Xlo[i] = __float2half_rn(f - __half2float(hi));
    }
}

// W[h*CC + k][e] -> Wt[h][e][k] (single fp16)
__global__ void convert_w_kernel(const float* __restrict__ w) {
    __shared__ float t[32][33];
    int h = blockIdx.z;
    int e0 = blockIdx.x * 32, k0 = blockIdx.y * 32;
    int tx = threadIdx.x, ty = threadIdx.y;  // (32, 8)
#pragma unroll
    for (int r = 0; r < 4; r++) {
        int k = k0 + ty + r * 8;
        t[ty + r * 8][tx] = w[(size_t)(h * CC + k) * CC + e0 + tx];
    }
    __syncthreads();
#pragma unroll
    for (int r = 0; r < 4; r++) {
        int e = e0 + ty + r * 8;
        size_t idx = (size_t)h * CC * CC + (size_t)e * CC + k0 + tx;
        g_Wt[idx] = __float2half_rn(t[tx][ty + r * 8]);
    }
}

// ---------------------------------------------------------------------------
// Softmax: row softmax over s<=t -> fp16 P; only touches s < roundup(t+1,128)
// ---------------------------------------------------------------------------
__global__ __launch_bounds__(256) void softmax_kernel() {
    __shared__ float red[8];
    int row = blockIdx.x;
    int t = (row / HH) & (TT - 1);
    int limit = ((t >> 7) + 1) << 7;  // causal extent rounded to 128
    const float* p = g_S + (size_t)row * TT;
    __half* po = g_P + (size_t)row * TT;
    int tid = threadIdx.x;

    float v[4];
    float m = -INFINITY;
#pragma unroll
    for (int j = 0; j < 4; j++) {
        int s = tid + j * 256;
        if (s <= t) { v[j] = p[s]; m = fmaxf(m, v[j]); }
        else v[j] = -INFINITY;
    }
#pragma unroll
    for (int o = 16; o; o >>= 1) m = fmaxf(m, __shfl_xor_sync(0xffffffffu, m, o));
    if ((tid & 31) == 0) red[tid >> 5] = m;
    __syncthreads();
    if (tid < 32) {
        float mm = (tid < 8) ? red[tid] : -INFINITY;
#pragma unroll
        for (int o = 4; o; o >>= 1) mm = fmaxf(mm, __shfl_xor_sync(0xffffffffu, mm, o));
        if (tid == 0) red[0] = mm;
    }
    __syncthreads();
    m = red[0];
    __syncthreads();

    float sum = 0.0f;
#pragma unroll
    for (int j = 0; j < 4; j++) {
        int s = tid + j * 256;
        if (s <= t) { v[j] = __expf(v[j] - m); sum += v[j]; }
        else v[j] = 0.0f;
    }
#pragma unroll
    for (int o = 16; o; o >>= 1) sum += __shfl_xor_sync(0xffffffffu, sum, o);
    if ((tid & 31) == 0) red[tid >> 5] = sum;
    __syncthreads();
    if (tid < 32) {
        float ss = (tid < 8) ? red[tid] : 0.0f;
#pragma unroll
        for (int o = 4; o; o >>= 1) ss += __shfl_xor_sync(0xffffffffu, ss, o);
        if (tid == 0) red[0] = ss;
    }
    __syncthreads();
    float inv = 1.0f / red[0];

#pragma unroll
    for (int j = 0; j < 4; j++) {
        int s = tid + j * 256;
        if (s < limit) po[s] = __float2half_rn(v[j] * inv);
    }
}

// ---------------------------------------------------------------------------
// HMMA fp16 GEMM template. 128x128 tile, K-chunk 32, 4-stage cp.async pipe.
// Stages 3/4: minBlocksPerMultiprocessor=2 (<=128 regs) so two CTAs co-reside
// per SM and cover each other's sync/LDSM gaps (tensor pipe was 44% at occ 1).
// STAGE==1: scores S = Y Y^T (K=64), hi/lo 3-pass, triangular grid
// STAGE==3: Z^T = (x @ W_h)^T, single-pass fp16, heads zoff..zoff+7 -> g_Zt
// STAGE==4: out = P @ Z, parts zoff..zoff+3 (2 heads each) + LPT -> g_Opart
// ---------------------------------------------------------------------------
constexpr int TSTRIDE = 80;               // padded smem row (bytes)
constexpr int TILE_B = 128 * TSTRIDE;     // 10240
constexpr int NBUF = 4;

template <int STAGE>
__global__ __launch_bounds__(256, (STAGE == 1) ? 1 : 2)
void mma_gemm(float* __restrict__ Out, int zoff) {
    constexpr int NA = (STAGE == 1) ? 2 : 1;   // # A tiles (hi[,lo])
    constexpr int NB = (STAGE == 1) ? 2 : 1;   // # B tiles (hi[,lo])
    constexpr int BUF_B = (NA + NB) * TILE_B;

    extern __shared__ char sp[];
    const uint32_t sbase = smem_u32(sp);

    const int tid = threadIdx.x;
    const int lane = tid & 31;
    const int wid = tid >> 5;
    const int wm = wid & 3;      // 4 warps along M (32 rows each)
    const int wn = wid >> 2;     // 2 warps along N (64 cols each)

    int m0, n0;
    if (STAGE == 1) {
        // triangular packing: blockIdx.x in [0,36) -> (tx <= ty)
        int i = blockIdx.x;
        int ty = (int)((sqrtf(8.0f * (float)i + 1.0f) - 1.0f) * 0.5f);
        while ((ty + 1) * (ty + 2) / 2 <= i) ty++;
        while (ty * (ty + 1) / 2 > i) ty--;
        int tx = i - ty * (ty + 1) / 2;
        m0 = ty * 128; n0 = tx * 128;
    } else if (STAGE == 4) {
        // LPT: heavy tiles (large by) first
        m0 = (gridDim.y - 1 - blockIdx.y) * 128; n0 = blockIdx.x * 128;
    } else {
        m0 = blockIdx.y * 128; n0 = blockIdx.x * 128;
    }
    const int by = m0 >> 7;

    int b, h = 0, part = 0;
    const __half *A0, *A1 = nullptr, *B0, *B1 = nullptr;
    size_t ldA, ldB;
    int NC, kph = 0;
    if (STAGE == 1) {
        int z = blockIdx.z; b = z >> 4; h = z & 15;
        A0 = g_Xhi + (size_t)b * TT * CC + h * DD;
        A1 = g_Xlo + (size_t)b * TT * CC + h * DD;
        B0 = A0; B1 = A1; ldA = CC; ldB = CC;
        NC = 2;
    } else if (STAGE == 3) {
        int z = blockIdx.z; b = z >> 3; h = zoff + (z & 7);   // 8 heads per launch
        A0 = g_Xhi + (size_t)b * TT * CC; ldA = CC;
        B0 = g_Wt + (size_t)h * CC * CC; ldB = CC;
        NC = 32;
    } else {
        int z = blockIdx.z; b = z >> 2; part = zoff + (z & 3); // 4 parts per launch
        A0 = g_P + (size_t)b * TT * HT; ldA = HT;
        B0 = g_Zt + (size_t)b * CC * HT; ldB = HT;
        kph = (by + 1) * 4;                // kept 32-chunks per head (causal)
        NC = (HH / NSPLIT) * kph;          // 2 heads per part
    }

    auto kk_of = [&](int i) -> int {
        if (STAGE == 4) return (part * (HH / NSPLIT) + i / kph) * TT + (i % kph) * 32;
        return i * 32;
    };

    const int lr = tid >> 1;
    const int lc = (tid & 1) * 2;
    auto load_tiles = [&](int i, int buf) {
        int kk = kk_of(i);
        uint32_t sb = sbase + buf * BUF_B + lr * TSTRIDE + lc * 16;
        size_t offA = (size_t)(m0 + lr) * ldA + kk + lc * 8;
        size_t offB = (size_t)(n0 + lr) * ldB + kk + lc * 8;
        cp16(sb, A0 + offA);
        cp16(sb + 16, A0 + offA + 8);
        if (NA == 2) {
            cp16(sb + TILE_B, A1 + offA);
            cp16(sb + TILE_B + 16, A1 + offA + 8);
        }
        cp16(sb + NA * TILE_B, B0 + offB);
        cp16(sb + NA * TILE_B + 16, B0 + offB + 8);
        if (NB == 2) {
            cp16(sb + (NA + 1) * TILE_B, B1 + offB);
            cp16(sb + (NA + 1) * TILE_B + 16, B1 + offB + 8);
        }
    };

    float acc[2][8][4];
#pragma unroll
    for (int i = 0; i < 2; i++)
#pragma unroll
        for (int j = 0; j < 8; j++)
#pragma unroll
            for (int k = 0; k < 4; k++) acc[i][j][k] = 0.0f;

    // prologue: always NBUF-1 committed groups (empty groups complete trivially)
#pragma unroll
    for (int j = 0; j < NBUF - 1; j++) {
        if (j < NC) load_tiles(j, j);
        cp_commit();
    }

    for (int i = 0; i < NC; ++i) {
        cp_wait<NBUF - 2>();
        __syncthreads();

        const uint32_t base = sbase + (i & (NBUF - 1)) * BUF_B;
#pragma unroll
        for (int ks = 0; ks < 2; ks++) {
            uint32_t afr[NA][2][4], bfr[NB][4][4];
#pragma unroll
            for (int mt = 0; mt < 2; mt++) {
                uint32_t a = base + (uint32_t)(wm * 32 + mt * 16 + (lane & 15)) * TSTRIDE
                             + ((lane >> 4) << 4) + ks * 32;
                LDSM4(afr[0][mt], a);
                if (NA == 2) LDSM4(afr[1][mt], a + TILE_B);
            }
#pragma unroll
            for (int q = 0; q < 4; q++) {
                uint32_t a = base + NA * TILE_B
                             + (uint32_t)(wn * 64 + q * 16 + ((lane >> 4) << 3) + (lane & 7)) * TSTRIDE
                             + (((lane >> 3) & 1) << 4) + ks * 32;
                LDSM4(bfr[0][q], a);
                if (NB == 2) LDSM4(bfr[1][q], a + TILE_B);
            }
            // compensation passes: skip lo*lo
#pragma unroll
            for (int ia = 0; ia < NA; ia++)
#pragma unroll
                for (int ib = 0; ib < NB; ib++) {
                    if (ia + ib == 2) continue;
#pragma unroll
                    for (int mt = 0; mt < 2; mt++)
#pragma unroll
                        for (int q = 0; q < 4; q++) {
                            mma_fp16(acc[mt][2 * q],     afr[ia][mt], &bfr[ib][q][0]);
                            mma_fp16(acc[mt][2 * q + 1], afr[ia][mt], &bfr[ib][q][2]);
                        }
                }
        }
        if (i + NBUF - 1 < NC) load_tiles(i + NBUF - 1, (i + NBUF - 1) & (NBUF - 1));
        cp_commit();
    }
    cp_wait<0>();
    __syncthreads();

    if (STAGE == 1) {
        int z = blockIdx.z;
        float* Cp = g_S + (size_t)(z >> 4) * TT * HT + (size_t)(z & 15) * TT;
#pragma unroll
        for (int mt = 0; mt < 2; mt++)
#pragma unroll
            for (int nt = 0; nt < 8; nt++)
#pragma unroll
                for (int ci = 0; ci < 4; ci++) {
                    int row = m0 + wm * 32 + mt * 16 + (lane >> 2) + (ci >> 1) * 8;
                    int col = n0 + wn * 64 + nt * 8 + ((lane & 3) << 1) + (ci & 1);
                    if (col <= row)  // masked region never read by softmax
                        Cp[(size_t)row * HT + col] = acc[mt][nt][ci] * 0.25f;
                }
    } else if (STAGE == 4) {
        float* ob = Out + ((size_t)part * BB + b) * TT * CC;
#pragma unroll
        for (int mt = 0; mt < 2; mt++)
#pragma unroll
            for (int nt = 0; nt < 8; nt++) {
                int row = m0 + wm * 32 + mt * 16 + (lane >> 2);
                int col = n0 + wn * 64 + nt * 8 + ((lane & 3) << 1);
                *reinterpret_cast<float2*>(&ob[(size_t)row * CC + col]) =
                    make_float2(acc[mt][nt][0], acc[mt][nt][1]);
                *reinterpret_cast<float2*>(&ob[(size_t)(row + 8) * CC + col]) =
                    make_float2(acc[mt][nt][2], acc[mt][nt][3]);
            }
    } else {
        // STAGE 3: transpose through smem, then coalesced Z^T fp16 stores
        constexpr int TROW = 272;             // 128*2 + 16 pad
#pragma unroll
        for (int mt = 0; mt < 2; mt++)
#pragma unroll
            for (int nt = 0; nt < 8; nt++)
#pragma unroll
                for (int ci = 0; ci < 4; ci++) {
                    int row = wm * 32 + mt * 16 + (lane >> 2) + (ci >> 1) * 8;  // m
                    int col = wn * 64 + nt * 8 + ((lane & 3) << 1) + (ci & 1);  // e
                    *reinterpret_cast<__half*>(sp + col * TROW + row * 2) =
                        __float2half_rn(acc[mt][nt][ci]);
                }
        __syncthreads();
        size_t gb = (size_t)b * CC * HT + (size_t)h * TT + m0;
        for (int idx = tid; idx < 128 * 16; idx += 256) {
            int r = idx >> 4, cch = idx & 15;
            uint4 v = *reinterpret_cast<uint4*>(sp + r * TROW + cch * 16);
            *reinterpret_cast<uint4*>(&g_Zt[gb + (size_t)(n0 + r) * HT + cch * 8]) = v;
        }
    }
}

// ---------------------------------------------------------------------------
// Sum the eight stage-4 head-split partials into the final output.
// ---------------------------------------------------------------------------
__global__ void add_out_kernel(float* __restrict__ out) {
    size_t n = (size_t)BB * TT * CC / 4;
    float4* o = reinterpret_cast<float4*>(out);
    for (size_t i = (size_t)blockIdx.x * blockDim.x + threadIdx.x; i < n;
         i += (size_t)gridDim.x * blockDim.x) {
        float x = 0, y = 0, z = 0, w = 0;
#pragma unroll
        for (int p = 0; p < NSPLIT; p++) {
            float4 v = reinterpret_cast<const float4*>(g_Opart[p])[i];
            x += v.x; y += v.y; z += v.z; w += v.w;
        }
        o[i] = make_float4(x, y, z, w);
    }
}

// ---------------------------------------------------------------------------
extern "C" void kernel_launch(void* const* d_in, const int* in_sizes, int n_in,
                              void* d_out, int out_size) {
    const float* x = (const float*)d_in[0];
    // d_in[1]: boolean causal mask == triu(k=1); applied analytically in-kernel.
    const float* w = (const float*)d_in[2];
    float* out = (float*)d_out;

    constexpr int DSMEM1 = NBUF * 4 * TILE_B;  // 163840 (NA=2, NB=2)
    constexpr int DSMEM34 = NBUF * 2 * TILE_B; // 81920  (NA=1, NB=1)

    cudaFuncSetAttribute(mma_gemm<1>, cudaFuncAttributeMaxDynamicSharedMemorySize, DSMEM1);
    cudaFuncSetAttribute(mma_gemm<3>, cudaFuncAttributeMaxDynamicSharedMemorySize, DSMEM34);
    cudaFuncSetAttribute(mma_gemm<4>, cudaFuncAttributeMaxDynamicSharedMemorySize, DSMEM34);

    float* o0;
    cudaGetSymbolAddress((void**)&o0, g_Opart);

    // One-time infra (no device memory): side stream + capture-legal events.
    static cudaStream_t sB = nullptr;
    static cudaEvent_t eFork = nullptr, eX = nullptr, eP = nullptr;
    static cudaEvent_t e3a = nullptr, eJoin = nullptr;
    if (sB == nullptr) {
        cudaStreamCreateWithFlags(&sB, cudaStreamNonBlocking);
        cudaEventCreateWithFlags(&eFork, cudaEventDisableTiming);
        cudaEventCreateWithFlags(&eX, cudaEventDisableTiming);
        cudaEventCreateWithFlags(&eP, cudaEventDisableTiming);
        cudaEventCreateWithFlags(&e3a, cudaEventDisableTiming);
        cudaEventCreateWithFlags(&eJoin, cudaEventDisableTiming);
    }

    // Fork immediately: branch B starts convert_w (depends only on w).
    cudaEventRecord(eFork, 0);
    cudaStreamWaitEvent(sB, eFork, 0);
    convert_w_kernel<<<dim3(32, 32, 16), dim3(32, 8), 0, sB>>>(w);

    convert_x_kernel<<<2048, 256>>>(x);
    cudaEventRecord(eX, 0);

    // Branch B: stage 3 in two head-halves.
    cudaStreamWaitEvent(sB, eX, 0);
    mma_gemm<3><<<dim3(CC / 128, TT / 128, BB * 8), 256, DSMEM34, sB>>>(nullptr, 0);
    cudaEventRecord(e3a, sB);
    mma_gemm<3><<<dim3(CC / 128, TT / 128, BB * 8), 256, DSMEM34, sB>>>(nullptr, 8);

    // Branch A: stage 1 (triangular grid) -> softmax.
    mma_gemm<1><<<dim3(36, 1, BB * HH), 256, DSMEM1>>>(nullptr, 0);
    softmax_kernel<<<BB * TT * HH, 256>>>();
    cudaEventRecord(eP, 0);

    // Stage 4 half 1 (heads 0-7) on main stream: needs softmax + e3a.
    cudaStreamWaitEvent(0, e3a, 0);
    mma_gemm<4><<<dim3(CC / 128, TT / 128, BB * 4), 256, DSMEM34>>>(o0, 0);

    // Stage 4 half 2 (heads 8-15) on side stream: needs stage3 half 2 + softmax.
    cudaStreamWaitEvent(sB, eP, 0);
    mma_gemm<4><<<dim3(CC / 128, TT / 128, BB * 4), 256, DSMEM34, sB>>>(o0, 4);
    cudaEventRecord(eJoin, sB);

    // Final sum after both halves.
    cudaStreamWaitEvent(0, eJoin, 0);
    add_out_kernel<<<1024, 256>>>(out);
}

// round 14
// speedup vs baseline: 1.2803x; 1.0085x over previous
#include <cuda_runtime.h>
#include <cuda_fp16.h>
#include <math.h>
#include <stdint.h>

// ---------------------------------------------------------------------------
// Problem constants
// ---------------------------------------------------------------------------
constexpr int BB = 2;
constexpr int TT = 1024;
constexpr int CC = 1024;
constexpr int DD = 64;
constexpr int HH = 16;
constexpr int HT = HH * TT;  // 16384

constexpr int NSPLIT = 8;    // stage-4 head splits (2 heads each)

// ---------------------------------------------------------------------------
// Device scratch
// ---------------------------------------------------------------------------
__device__ float  g_S   [(size_t)BB * TT * HT];     // fp32 scores
__device__ __half g_P   [(size_t)BB * TT * HT];     // softmax probs (fp16)
__device__ __half g_Zt  [(size_t)BB * CC * HT];     // Z^T fp16 [b][e][h*T+s]
__device__ __half g_Xhi [(size_t)BB * TT * CC];     // x hi
__device__ __half g_Xlo [(size_t)BB * TT * CC];     // x lo (scores only)
__device__ __half g_Wt  [(size_t)HH * CC * CC];     // W^T fp16 [h][e][k]
__device__ float  g_Opart[NSPLIT][(size_t)BB * TT * CC]; // stage-4 partials

// ---------------------------------------------------------------------------
// Baseline-PTX helpers (compute_103-safe; no "a"-only features)
// ---------------------------------------------------------------------------
__device__ __forceinline__ uint32_t smem_u32(const void* p) {
    uint32_t a;
    asm("{ .reg .u64 t; cvta.to.shared.u64 t, %1; cvt.u32.u64 %0, t; }" : "=r"(a) : "l"(p));
    return a;
}
__device__ __forceinline__ void cp16(uint32_t saddr, const void* g) {
    asm volatile("cp.async.cg.shared.global [%0], [%1], 16;" :: "r"(saddr), "l"(g));
}
__device__ __forceinline__ void cp_commit() {
    asm volatile("cp.async.commit_group;" ::: "memory");
}
template <int N>
__device__ __forceinline__ void cp_wait() {
    asm volatile("cp.async.wait_group %0;" :: "n"(N) : "memory");
}
#define LDSM4(R, A)                                                               \
    asm volatile("ldmatrix.sync.aligned.m8n8.x4.shared.b16 {%0,%1,%2,%3}, [%4];"  \
                 : "=r"((R)[0]), "=r"((R)[1]), "=r"((R)[2]), "=r"((R)[3]) : "r"(A))

__device__ __forceinline__ void mma_fp16(float* c, const uint32_t* a, const uint32_t* b) {
    asm volatile(
        "mma.sync.aligned.m16n8k16.row.col.f32.f16.f16.f32 "
        "{%0,%1,%2,%3},{%4,%5,%6,%7},{%8,%9},{%0,%1,%2,%3};"
        : "+f"(c[0]), "+f"(c[1]), "+f"(c[2]), "+f"(c[3])
        : "r"(a[0]), "r"(a[1]), "r"(a[2]), "r"(a[3]), "r"(b[0]), "r"(b[1]));
}

// ---------------------------------------------------------------------------
// Conversions
// ---------------------------------------------------------------------------
__global__ void convert_x_kernel(const float* __restrict__ x) {
    size_t n = (size_t)BB * TT * CC;
    for (size_t i = (size_t)blockIdx.x * blockDim.x + threadIdx.x; i < n;
         i += (size_t)gridDim.x * blockDim.x) {
        float f = x[i];
        __half hi = __float2half_rn(f);
        g_Xhi[i] = hi;
        g_Xlo[i] = __float2half_rn(f - __half2float(hi));
    }
}

// W[h*CC + k][e] -> Wt[h][e][k] (single fp16)
__global__ void convert_w_kernel(const float* __restrict__ w) {
    __shared__ float t[32][33];
    int h = blockIdx.z;
    int e0 = blockIdx.x * 32, k0 = blockIdx.y * 32;
    int tx = threadIdx.x, ty = threadIdx.y;  // (32, 8)
#pragma unroll
    for (int r = 0; r < 4; r++) {
        int k = k0 + ty + r * 8;
        t[ty + r * 8][tx] = w[(size_t)(h * CC + k) * CC + e0 + tx];
    }
    __syncthreads();
#pragma unroll
    for (int r = 0; r < 4; r++) {
        int e = e0 + ty + r * 8;
        size_t idx = (size_t)h * CC * CC + (size_t)e * CC + k0 + tx;
        g_Wt[idx] = __float2half_rn(t[tx][ty + r * 8]);
    }
}

// ---------------------------------------------------------------------------
// Softmax: row softmax over s<=t -> fp16 P; only touches s < roundup(t+1,128)
// ---------------------------------------------------------------------------
__global__ __launch_bounds__(256) void softmax_kernel() {
    __shared__ float red[8];
    int row = blockIdx.x;
    int t = (row / HH) & (TT - 1);
    int limit = ((t >> 7) + 1) << 7;  // causal extent rounded to 128
    const float* p = g_S + (size_t)row * TT;
    __half* po = g_P + (size_t)row * TT;
    int tid = threadIdx.x;

    float v[4];
    float m = -INFINITY;
#pragma unroll
    for (int j = 0; j < 4; j++) {
        int s = tid + j * 256;
        if (s <= t) { v[j] = p[s]; m = fmaxf(m, v[j]); }
        else v[j] = -INFINITY;
    }
#pragma unroll
    for (int o = 16; o; o >>= 1) m = fmaxf(m, __shfl_xor_sync(0xffffffffu, m, o));
    if ((tid & 31) == 0) red[tid >> 5] = m;
    __syncthreads();
    if (tid < 32) {
        float mm = (tid < 8) ? red[tid] : -INFINITY;
#pragma unroll
        for (int o = 4; o; o >>= 1) mm = fmaxf(mm, __shfl_xor_sync(0xffffffffu, mm, o));
        if (tid == 0) red[0] = mm;
    }
    __syncthreads();
    m = red[0];
    __syncthreads();

    float sum = 0.0f;
#pragma unroll
    for (int j = 0; j < 4; j++) {
        int s = tid + j * 256;
        if (s <= t) { v[j] = __expf(v[j] - m); sum += v[j]; }
        else v[j] = 0.0f;
    }
#pragma unroll
    for (int o = 16; o; o >>= 1) sum += __shfl_xor_sync(0xffffffffu, sum, o);
    if ((tid & 31) == 0) red[tid >> 5] = sum;
    __syncthreads();
    if (tid < 32) {
        float ss = (tid < 8) ? red[tid] : 0.0f;
#pragma unroll
        for (int o = 4; o; o >>= 1) ss += __shfl_xor_sync(0xffffffffu, ss, o);
        if (tid == 0) red[0] = ss;
    }
    __syncthreads();
    float inv = 1.0f / red[0];

#pragma unroll
    for (int j = 0; j < 4; j++) {
        int s = tid + j * 256;
        if (s < limit) po[s] = __float2half_rn(v[j] * inv);
    }
}

// ---------------------------------------------------------------------------
// HMMA fp16 GEMM template. K-chunk 32, 4-stage cp.async pipe.
// STAGE==1: 128x128 tile, warp 32x64 (4x2), hi/lo 3-pass, triangular grid
// STAGE==3/4: 128x256 tile, warp 64x64 (2x4) -- halves smem traffic per FLOP
//   (R13 showed stages 3/4 are smem-crossbar-bound at 192B/MMA; this is 128B)
// STAGE==3: Z^T = (x @ W_h)^T, single-pass fp16, heads zoff..zoff+7 -> g_Zt
// STAGE==4: out = P @ Z, parts zoff..zoff+3 (2 heads each) + LPT -> g_Opart
// ---------------------------------------------------------------------------
constexpr int TSTRIDE = 80;               // padded smem row (bytes)
constexpr int TILE_B = 128 * TSTRIDE;     // 10240 (128-row tile)
constexpr int BTILE_B = 256 * TSTRIDE;    // 20480 (256-row tile, stages 3/4)
constexpr int NBUF = 4;

template <int STAGE>
__global__ __launch_bounds__(256, 1)
void mma_gemm(float* __restrict__ Out, int zoff) {
    constexpr int NA = (STAGE == 1) ? 2 : 1;   // # A tiles (hi[,lo])
    constexpr int NB = (STAGE == 1) ? 2 : 1;   // # B tiles (hi[,lo])
    constexpr int NT = (STAGE == 1) ? 128 : 256;  // CTA tile N
    constexpr int MT = (STAGE == 1) ? 2 : 4;      // m16 tiles per warp
    constexpr int BUF_B = (STAGE == 1) ? (4 * TILE_B) : (TILE_B + BTILE_B);
    constexpr int BOFF = (STAGE == 1) ? (2 * TILE_B) : TILE_B;  // B region offset

    extern __shared__ char sp[];
    const uint32_t sbase = smem_u32(sp);

    const int tid = threadIdx.x;
    const int lane = tid & 31;
    const int wid = tid >> 5;
    // warp layout: stage1 4x2 (32-row x 64-col); stages 3/4 2x4 (64-row x 64-col)
    const int wm = (STAGE == 1) ? (wid & 3) : (wid & 1);
    const int wn = (STAGE == 1) ? (wid >> 2) : (wid >> 1);
    const int MROW = (STAGE == 1) ? 32 : 64;   // rows per wm step

    int m0, n0;
    if (STAGE == 1) {
        // triangular packing: blockIdx.x in [0,36) -> (tx <= ty)
        int i = blockIdx.x;
        int ty = (int)((sqrtf(8.0f * (float)i + 1.0f) - 1.0f) * 0.5f);
        while ((ty + 1) * (ty + 2) / 2 <= i) ty++;
        while (ty * (ty + 1) / 2 > i) ty--;
        int tx = i - ty * (ty + 1) / 2;
        m0 = ty * 128; n0 = tx * 128;
    } else if (STAGE == 4) {
        // LPT: heavy tiles (large by) first
        m0 = (gridDim.y - 1 - blockIdx.y) * 128; n0 = blockIdx.x * NT;
    } else {
        m0 = blockIdx.y * 128; n0 = blockIdx.x * NT;
    }
    const int by = m0 >> 7;

    int b, h = 0, part = 0;
    const __half *A0, *A1 = nullptr, *B0, *B1 = nullptr;
    size_t ldA, ldB;
    int NC, kph = 0;
    if (STAGE == 1) {
        int z = blockIdx.z; b = z >> 4; h = z & 15;
        A0 = g_Xhi + (size_t)b * TT * CC + h * DD;
        A1 = g_Xlo + (size_t)b * TT * CC + h * DD;
        B0 = A0; B1 = A1; ldA = CC; ldB = CC;
        NC = 2;
    } else if (STAGE == 3) {
        int z = blockIdx.z; b = z >> 3; h = zoff + (z & 7);   // 8 heads per launch
        A0 = g_Xhi + (size_t)b * TT * CC; ldA = CC;
        B0 = g_Wt + (size_t)h * CC * CC; ldB = CC;
        NC = 32;
    } else {
        int z = blockIdx.z; b = z >> 2; part = zoff + (z & 3); // 4 parts per launch
        A0 = g_P + (size_t)b * TT * HT; ldA = HT;
        B0 = g_Zt + (size_t)b * CC * HT; ldB = HT;
        kph = (by + 1) * 4;                // kept 32-chunks per head (causal)
        NC = (HH / NSPLIT) * kph;          // 2 heads per part
    }

    auto kk_of = [&](int i) -> int {
        if (STAGE == 4) return (part * (HH / NSPLIT) + i / kph) * TT + (i % kph) * 32;
        return i * 32;
    };

    const int lr = tid >> 1;
    const int lcb = (tid & 1) * 32;         // byte offset within 64B row
    auto load_tiles = [&](int i, int buf) {
        int kk = kk_of(i);
        if (STAGE == 1) {
            uint32_t sb = sbase + buf * BUF_B + lr * TSTRIDE + lcb;
            size_t offA = (size_t)(m0 + lr) * ldA + kk + lcb / 2;
            size_t offB = (size_t)(n0 + lr) * ldB + kk + lcb / 2;
            cp16(sb, A0 + offA);
            cp16(sb + 16, A0 + offA + 8);
            cp16(sb + TILE_B, A1 + offA);
            cp16(sb + TILE_B + 16, A1 + offA + 8);
            cp16(sb + 2 * TILE_B, B0 + offB);
            cp16(sb + 2 * TILE_B + 16, B0 + offB + 8);
            cp16(sb + 3 * TILE_B, B1 + offB);
            cp16(sb + 3 * TILE_B + 16, B1 + offB + 8);
        } else {
            // A: 128 rows
            uint32_t sbA = sbase + buf * BUF_B + lr * TSTRIDE + lcb;
            size_t offA = (size_t)(m0 + lr) * ldA + kk + lcb / 2;
            cp16(sbA, A0 + offA);
            cp16(sbA + 16, A0 + offA + 8);
            // B: 256 rows, two passes
#pragma unroll
            for (int r2 = 0; r2 < 2; r2++) {
                int row = lr + r2 * 128;
                uint32_t sbB = sbase + buf * BUF_B + BOFF + row * TSTRIDE + lcb;
                size_t offB = (size_t)(n0 + row) * ldB + kk + lcb / 2;
                cp16(sbB, B0 + offB);
                cp16(sbB + 16, B0 + offB + 8);
            }
        }
    };

    float acc[MT][8][4];
#pragma unroll
    for (int i = 0; i < MT; i++)
#pragma unroll
        for (int j = 0; j < 8; j++)
#pragma unroll
            for (int k = 0; k < 4; k++) acc[i][j][k] = 0.0f;

    // prologue: always NBUF-1 committed groups (empty groups complete trivially)
#pragma unroll
    for (int j = 0; j < NBUF - 1; j++) {
        if (j < NC) load_tiles(j, j);
        cp_commit();
    }

    for (int i = 0; i < NC; ++i) {
        cp_wait<NBUF - 2>();
        __syncthreads();

        const uint32_t base = sbase + (i & (NBUF - 1)) * BUF_B;
#pragma unroll
        for (int ks = 0; ks < 2; ks++) {
            uint32_t afr[NA][MT][4], bfr[NB][4][4];
#pragma unroll
            for (int mt = 0; mt < MT; mt++) {
                uint32_t a = base + (uint32_t)(wm * MROW + mt * 16 + (lane & 15)) * TSTRIDE
                             + ((lane >> 4) << 4) + ks * 32;
                LDSM4(afr[0][mt], a);
                if (NA == 2) LDSM4(afr[1][mt], a + TILE_B);
            }
#pragma unroll
            for (int q = 0; q < 4; q++) {
                uint32_t a = base + BOFF
                             + (uint32_t)(wn * 64 + q * 16 + ((lane >> 4) << 3) + (lane & 7)) * TSTRIDE
                             + (((lane >> 3) & 1) << 4) + ks * 32;
                LDSM4(bfr[0][q], a);
                if (NB == 2) LDSM4(bfr[1][q], a + (STAGE == 1 ? TILE_B : 0));
            }
            // compensation passes: skip lo*lo
#pragma unroll
            for (int ia = 0; ia < NA; ia++)
#pragma unroll
                for (int ib = 0; ib < NB; ib++) {
                    if (ia + ib == 2) continue;
#pragma unroll
                    for (int mt = 0; mt < MT; mt++)
#pragma unroll
                        for (int q = 0; q < 4; q++) {
                            mma_fp16(acc[mt][2 * q],     afr[ia][mt], &bfr[ib][q][0]);
                            mma_fp16(acc[mt][2 * q + 1], afr[ia][mt], &bfr[ib][q][2]);
                        }
                }
        }
        if (i + NBUF - 1 < NC) load_tiles(i + NBUF - 1, (i + NBUF - 1) & (NBUF - 1));
        cp_commit();
    }
    cp_wait<0>();
    __syncthreads();

    if (STAGE == 1) {
        int z = blockIdx.z;
        float* Cp = g_S + (size_t)(z >> 4) * TT * HT + (size_t)(z & 15) * TT;
#pragma unroll
        for (int mt = 0; mt < MT; mt++)
#pragma unroll
            for (int nt = 0; nt < 8; nt++)
#pragma unroll
                for (int ci = 0; ci < 4; ci++) {
                    int row = m0 + wm * MROW + mt * 16 + (lane >> 2) + (ci >> 1) * 8;
                    int col = n0 + wn * 64 + nt * 8 + ((lane & 3) << 1) + (ci & 1);
                    if (col <= row)  // masked region never read by softmax
                        Cp[(size_t)row * HT + col] = acc[mt][nt][ci] * 0.25f;
                }
    } else if (STAGE == 4) {
        float* ob = Out + ((size_t)part * BB + b) * TT * CC;
#pragma unroll
        for (int mt = 0; mt < MT; mt++)
#pragma unroll
            for (int nt = 0; nt < 8; nt++) {
                int row = m0 + wm * MROW + mt * 16 + (lane >> 2);
                int col = n0 + wn * 64 + nt * 8 + ((lane & 3) << 1);
                *reinterpret_cast<float2*>(&ob[(size_t)row * CC + col]) =
                    make_float2(acc[mt][nt][0], acc[mt][nt][1]);
                *reinterpret_cast<float2*>(&ob[(size_t)(row + 8) * CC + col]) =
                    make_float2(acc[mt][nt][2], acc[mt][nt][3]);
            }
    } else {
        // STAGE 3: transpose through smem, then coalesced Z^T fp16 stores
        constexpr int TROW = 272;             // 128*2 + 16 pad
#pragma unroll
        for (int mt = 0; mt < MT; mt++)
#pragma unroll
            for (int nt = 0; nt < 8; nt++)
#pragma unroll
                for (int ci = 0; ci < 4; ci++) {
                    int row = wm * MROW + mt * 16 + (lane >> 2) + (ci >> 1) * 8;  // m 0..127
                    int col = wn * 64 + nt * 8 + ((lane & 3) << 1) + (ci & 1);    // e 0..255
                    *reinterpret_cast<__half*>(sp + col * TROW + row * 2) =
                        __float2half_rn(acc[mt][nt][ci]);
                }
        __syncthreads();
        size_t gb = (size_t)b * CC * HT + (size_t)h * TT + m0;
        for (int idx = tid; idx < NT * 16; idx += 256) {
            int r = idx >> 4, cch = idx & 15;
            uint4 v = *reinterpret_cast<uint4*>(sp + r * TROW + cch * 16);
            *reinterpret_cast<uint4*>(&g_Zt[gb + (size_t)(n0 + r) * HT + cch * 8]) = v;
        }
    }
}

// ---------------------------------------------------------------------------
// Sum the eight stage-4 head-split partials into the final output.
// ---------------------------------------------------------------------------
__global__ void add_out_kernel(float* __restrict__ out) {
    size_t n = (size_t)BB * TT * CC / 4;
    float4* o = reinterpret_cast<float4*>(out);
    for (size_t i = (size_t)blockIdx.x * blockDim.x + threadIdx.x; i < n;
         i += (size_t)gridDim.x * blockDim.x) {
        float x = 0, y = 0, z = 0, w = 0;
#pragma unroll
        for (int p = 0; p < NSPLIT; p++) {
            float4 v = reinterpret_cast<const float4*>(g_Opart[p])[i];
            x += v.x; y += v.y; z += v.z; w += v.w;
        }
        o[i] = make_float4(x, y, z, w);
    }
}

// ---------------------------------------------------------------------------
extern "C" void kernel_launch(void* const* d_in, const int* in_sizes, int n_in,
                              void* d_out, int out_size) {
    const float* x = (const float*)d_in[0];
    // d_in[1]: boolean causal mask == triu(k=1); applied analytically in-kernel.
    const float* w = (const float*)d_in[2];
    float* out = (float*)d_out;

    constexpr int DSMEM1 = NBUF * 4 * TILE_B;           // 163840
    constexpr int DSMEM34 = NBUF * (TILE_B + BTILE_B);  // 122880

    cudaFuncSetAttribute(mma_gemm<1>, cudaFuncAttributeMaxDynamicSharedMemorySize, DSMEM1);
    cudaFuncSetAttribute(mma_gemm<3>, cudaFuncAttributeMaxDynamicSharedMemorySize, DSMEM34);
    cudaFuncSetAttribute(mma_gemm<4>, cudaFuncAttributeMaxDynamicSharedMemorySize, DSMEM34);

    float* o0;
    cudaGetSymbolAddress((void**)&o0, g_Opart);

    // One-time infra (no device memory): side stream + capture-legal events.
    static cudaStream_t sB = nullptr;
    static cudaEvent_t eFork = nullptr, eX = nullptr, eP = nullptr;
    static cudaEvent_t e3a = nullptr, eJoin = nullptr;
    if (sB == nullptr) {
        cudaStreamCreateWithFlags(&sB, cudaStreamNonBlocking);
        cudaEventCreateWithFlags(&eFork, cudaEventDisableTiming);
        cudaEventCreateWithFlags(&eX, cudaEventDisableTiming);
        cudaEventCreateWithFlags(&eP, cudaEventDisableTiming);
        cudaEventCreateWithFlags(&e3a, cudaEventDisableTiming);
        cudaEventCreateWithFlags(&eJoin, cudaEventDisableTiming);
    }

    // Fork immediately: branch B starts convert_w (depends only on w).
    cudaEventRecord(eFork, 0);
    cudaStreamWaitEvent(sB, eFork, 0);
    convert_w_kernel<<<dim3(32, 32, 16), dim3(32, 8), 0, sB>>>(w);

    convert_x_kernel<<<2048, 256>>>(x);
    cudaEventRecord(eX, 0);

    // Branch B: stage 3 in two head-halves.
    cudaStreamWaitEvent(sB, eX, 0);
    mma_gemm<3><<<dim3(CC / 256, TT / 128, BB * 8), 256, DSMEM34, sB>>>(nullptr, 0);
    cudaEventRecord(e3a, sB);
    mma_gemm<3><<<dim3(CC / 256, TT / 128, BB * 8), 256, DSMEM34, sB>>>(nullptr, 8);

    // Branch A: stage 1 (triangular grid) -> softmax.
    mma_gemm<1><<<dim3(36, 1, BB * HH), 256, DSMEM1>>>(nullptr, 0);
    softmax_kernel<<<BB * TT * HH, 256>>>();
    cudaEventRecord(eP, 0);

    // Stage 4 half 1 (heads 0-7) on main stream: needs softmax + e3a.
    cudaStreamWaitEvent(0, e3a, 0);
    mma_gemm<4><<<dim3(CC / 256, TT / 128, BB * 4), 256, DSMEM34>>>(o0, 0);

    // Stage 4 half 2 (heads 8-15) on side stream: needs stage3 half 2 + softmax.
    cudaStreamWaitEvent(sB, eP, 0);
    mma_gemm<4><<<dim3(CC / 256, TT / 128, BB * 4), 256, DSMEM34, sB>>>(o0, 4);
    cudaEventRecord(eJoin, sB);

    // Final sum after both halves.
    cudaStreamWaitEvent(0, eJoin, 0);
    add_out_kernel<<<1024, 256>>>(out);
}